// round 2
// baseline (speedup 1.0000x reference)
#include <cuda_runtime.h>
#include <math.h>

// Problem constants
#define B_ 8
#define C_ 256
#define N_ 4096
#define H_ 8
#define D_ 32
#define P_ 64

// Scratch (device globals; allocation-free contract)
// g_proj layout: [slab][b][row256][n] where slab = proj*3+comp:
//   0=q_sa, 1=k_sa, 2=v_sa, 3=q_c, 4=k_c, 5=v_c ; row256 = h*32+d
__device__ float g_proj[6u * 8u * 256u * 4096u];      // 201 MB
__device__ float g_inv[3 * 2048];                     // 1/max(||row||,eps) for q_sa,q_c,k_c
__device__ float g_kvp[8][2 * 64 * 32 * 64];          // split partials for kv projection
__device__ float g_kv[2 * 64 * 32 * 64];              // [s][bh][d][p]  s:0=k_proj,1=v_proj
__device__ float g_attn[64 * 32 * 32];                // channel attention [bh][d][e]
__device__ float g_xsa[8u * 8u * 32u * 4096u];        // spatial out [b][h][d][n], 33.5 MB

// ---------------------------------------------------------------------------
// K1: QKV projections. out[m, n] = sum_c W[row(m), c] * x[b, c, n]
// M = 1536 rows (6 components of 256), N = 4096, K = 256, per batch b.
// 128x128x16 tile, 256 threads, 8x8 microtile.
// ---------------------------------------------------------------------------
__global__ __launch_bounds__(256) void k1_gemm(const float* __restrict__ x,
                                               const float* __restrict__ Wsa,
                                               const float* __restrict__ Wsc) {
    const int b  = blockIdx.z;
    const int m0 = blockIdx.y * 128;
    const int n0 = blockIdx.x * 128;
    const int p  = (m0 >= 768) ? 1 : 0;          // 0: spatial proj, 1: channel proj
    const int rbase = m0 - p * 768;              // row within this projection
    const int t  = rbase >> 8;                   // component 0,1,2 (block never straddles)
    const float* Wp = p ? Wsc : Wsa;
    // spatial needs components {q,k,v}={rows 0:256,256:512,768:1024} (skip 512:768)
    const int wbase = rbase + ((p == 0 && t == 2) ? 256 : 0);
    const float* xb = x + (size_t)b * C_ * N_;

    __shared__ float As[16][132];   // [k][m], padded (132 % 4 == 0 -> float4-aligned)
    __shared__ float Bs[16][128];   // [k][n]

    const int tid = threadIdx.x;
    const int tm = (tid >> 4) * 8;
    const int tn = (tid & 15) * 8;

    float acc[8][8];
#pragma unroll
    for (int i = 0; i < 8; i++)
#pragma unroll
        for (int j = 0; j < 8; j++) acc[i][j] = 0.f;

    for (int k0 = 0; k0 < 256; k0 += 16) {
        // load A tile: 128 rows x 16 k
#pragma unroll
        for (int i = 0; i < 2; i++) {
            int f = tid + i * 256;
            int m = f >> 2, kq = f & 3;
            float4 v = *(const float4*)(Wp + (size_t)(wbase + m) * 256 + k0 + kq * 4);
            As[kq * 4 + 0][m] = v.x;
            As[kq * 4 + 1][m] = v.y;
            As[kq * 4 + 2][m] = v.z;
            As[kq * 4 + 3][m] = v.w;
        }
        // load B tile: 16 k x 128 n
#pragma unroll
        for (int i = 0; i < 2; i++) {
            int f = tid + i * 256;
            int kk = f >> 5, nq = f & 31;
            *(float4*)&Bs[kk][nq * 4] =
                *(const float4*)(xb + (size_t)(k0 + kk) * N_ + n0 + nq * 4);
        }
        __syncthreads();
#pragma unroll
        for (int k = 0; k < 16; k++) {
            float a[8], bb[8];
            *(float4*)&a[0]  = *(const float4*)&As[k][tm];
            *(float4*)&a[4]  = *(const float4*)&As[k][tm + 4];
            *(float4*)&bb[0] = *(const float4*)&Bs[k][tn];
            *(float4*)&bb[4] = *(const float4*)&Bs[k][tn + 4];
#pragma unroll
            for (int i = 0; i < 8; i++)
#pragma unroll
                for (int j = 0; j < 8; j++) acc[i][j] += a[i] * bb[j];
        }
        __syncthreads();
    }

    float* ob = g_proj + (((size_t)(p * 3 + t) * 8 + b) * 256 + (rbase & 255)) * (size_t)N_;
#pragma unroll
    for (int i = 0; i < 8; i++) {
        float* orow = ob + (size_t)(tm + i) * N_ + n0 + tn;
        *(float4*)&orow[0] = make_float4(acc[i][0], acc[i][1], acc[i][2], acc[i][3]);
        *(float4*)&orow[4] = make_float4(acc[i][4], acc[i][5], acc[i][6], acc[i][7]);
    }
}

// ---------------------------------------------------------------------------
// K2: row L2 norms over N for q_sa (slab 0), q_c (slab 3), k_c (slab 4)
// ---------------------------------------------------------------------------
__global__ __launch_bounds__(256) void k2_norm() {
    int which = blockIdx.y;                    // 0,1,2
    int row = blockIdx.x;                      // 0..2047
    int slab = (which == 0) ? 0 : (which == 1 ? 3 : 4);
    const float* src = g_proj + ((size_t)slab * 2048 + row) * N_;
    int tid = threadIdx.x;
    float s = 0.f;
    for (int i = tid; i < N_; i += 256) { float v = src[i]; s += v * v; }
    __shared__ float red[8];
#pragma unroll
    for (int o = 16; o > 0; o >>= 1) s += __shfl_down_sync(0xffffffffu, s, o);
    if ((tid & 31) == 0) red[tid >> 5] = s;
    __syncthreads();
    if (tid < 8) {
        s = red[tid];
#pragma unroll
        for (int o = 4; o > 0; o >>= 1) s += __shfl_down_sync(0xffu, s, o);
        if (tid == 0) g_inv[which * 2048 + row] = 1.f / fmaxf(sqrtf(s), 1e-12f);
    }
}

// ---------------------------------------------------------------------------
// K3: Linformer projection: g_kv[s][bh][d][p] = sum_n T[s][bh][d][n] * EF[n][p]
// split over n (grid.y = 8) into partials, reduced by k3r.
// ---------------------------------------------------------------------------
__global__ __launch_bounds__(256) void k3_kvproj(const float* __restrict__ EF) {
    int s  = blockIdx.x >> 6;
    int bh = blockIdx.x & 63;
    int sp = blockIdx.y;
    const float* src = g_proj + ((size_t)(1 + s) * 2048 + bh * 32) * N_;  // slab 1=k, 2=v
    __shared__ float EFs[64][64];
    __shared__ float Xs[32][65];
    int tid = threadIdx.x;
    int dd = tid & 31, pg = tid >> 5;        // thread owns (dd, p = pg*8 .. pg*8+7)
    float acc[8];
#pragma unroll
    for (int j = 0; j < 8; j++) acc[j] = 0.f;

    for (int c = 0; c < 8; c++) {
        int nb = sp * 512 + c * 64;
#pragma unroll
        for (int i = 0; i < 4; i++) {
            int f = tid + i * 256;
            int nn = f >> 4, pq = f & 15;
            *(float4*)&EFs[nn][pq * 4] = *(const float4*)(EF + (size_t)(nb + nn) * 64 + pq * 4);
        }
#pragma unroll
        for (int i = 0; i < 8; i++) {
            int f = tid + i * 256;
            int r = f >> 6, j = f & 63;
            Xs[r][j] = src[(size_t)r * N_ + nb + j];
        }
        __syncthreads();
#pragma unroll 4
        for (int nn = 0; nn < 64; nn++) {
            float xv = Xs[dd][nn];
            float4 e0 = *(const float4*)&EFs[nn][pg * 8];
            float4 e1 = *(const float4*)&EFs[nn][pg * 8 + 4];
            acc[0] += xv * e0.x; acc[1] += xv * e0.y;
            acc[2] += xv * e0.z; acc[3] += xv * e0.w;
            acc[4] += xv * e1.x; acc[5] += xv * e1.y;
            acc[6] += xv * e1.z; acc[7] += xv * e1.w;
        }
        __syncthreads();
    }
    float* o = &g_kvp[sp][((s * 64 + bh) * 32 + dd) * 64 + pg * 8];
    *(float4*)&o[0] = make_float4(acc[0], acc[1], acc[2], acc[3]);
    *(float4*)&o[4] = make_float4(acc[4], acc[5], acc[6], acc[7]);
}

__global__ __launch_bounds__(256) void k3r_reduce() {
    int i = blockIdx.x * 256 + threadIdx.x;     // 262144 total
    float s = 0.f;
#pragma unroll
    for (int sp = 0; sp < 8; sp++) s += g_kvp[sp][i];
    g_kv[i] = s;
}

// ---------------------------------------------------------------------------
// K4: spatial attention. Per (bh, n): s[p]=sum_d qn[d]*Kp[d][p]; softmax over P;
//     o[d]=sum_p prob[p]*Vp[d][p]. Writes g_xsa[b][h][d][n].
// ---------------------------------------------------------------------------
__global__ __launch_bounds__(256) void k4_spatial(const float* __restrict__ temp2_sa) {
    int ch = blockIdx.x, bh = blockIdx.y;
    int h = bh & 7;
    __shared__ float Ks[32][64], Vs[32][64];
    int tid = threadIdx.x;
    float* ksf = &Ks[0][0];
    float* vsf = &Vs[0][0];
    for (int i = tid; i < 2048; i += 256) {
        ksf[i] = g_kv[(0 * 64 + bh) * 2048 + i];
        vsf[i] = g_kv[(1 * 64 + bh) * 2048 + i];
    }
    __syncthreads();

    int n = ch * 256 + tid;
    const float* qb = g_proj + (size_t)(bh * 32) * N_ + n;   // slab 0 (q_sa)
    const float* iv = g_inv + bh * 32;
    float temp = temp2_sa[h];

    float qn[32];
#pragma unroll
    for (int d = 0; d < 32; d++) qn[d] = qb[(size_t)d * N_] * iv[d];

    float s[64];
#pragma unroll
    for (int j = 0; j < 64; j++) s[j] = 0.f;
#pragma unroll
    for (int d = 0; d < 32; d++) {
        float q = qn[d];
#pragma unroll
        for (int pq = 0; pq < 16; pq++) {
            float4 k4 = *(const float4*)&Ks[d][pq * 4];
            s[pq * 4 + 0] += q * k4.x;
            s[pq * 4 + 1] += q * k4.y;
            s[pq * 4 + 2] += q * k4.z;
            s[pq * 4 + 3] += q * k4.w;
        }
    }
    float mx = -1e30f;
#pragma unroll
    for (int j = 0; j < 64; j++) { s[j] *= temp; mx = fmaxf(mx, s[j]); }
    float sum = 0.f;
#pragma unroll
    for (int j = 0; j < 64; j++) { float e = __expf(s[j] - mx); s[j] = e; sum += e; }
    float isum = 1.f / sum;

    float* ob = g_xsa + (size_t)(bh * 32) * N_ + n;
#pragma unroll
    for (int d = 0; d < 32; d++) {
        float o = 0.f;
#pragma unroll
        for (int pq = 0; pq < 16; pq++) {
            float4 v4 = *(const float4*)&Vs[d][pq * 4];
            o += s[pq * 4 + 0] * v4.x + s[pq * 4 + 1] * v4.y +
                 s[pq * 4 + 2] * v4.z + s[pq * 4 + 3] * v4.w;
        }
        ob[(size_t)d * N_] = o * isum;
    }
}

// ---------------------------------------------------------------------------
// K5: channel gram + softmax. attn[d][e] = softmax_e( qn[d,:]·kn[e,:] * temp )
// ---------------------------------------------------------------------------
__global__ __launch_bounds__(256) void k5_gram(const float* __restrict__ temp_sc) {
    int bh = blockIdx.x;
    int h = bh & 7;
    __shared__ float qcs[32][133], kcs[32][133];
    __shared__ float att[32][33];
    int tid = threadIdx.x;
    int ddp = tid >> 4, ep = tid & 15;       // 2x2 output tile per thread
    float a00 = 0.f, a01 = 0.f, a10 = 0.f, a11 = 0.f;
    const float* qsrc = g_proj + ((size_t)3 * 2048 + bh * 32) * N_;
    const float* ksrc = g_proj + ((size_t)4 * 2048 + bh * 32) * N_;

    for (int c0 = 0; c0 < N_; c0 += 128) {
#pragma unroll
        for (int i = 0; i < 16; i++) {
            int f = tid + i * 256;
            int r = f >> 7, j = f & 127;
            qcs[r][j] = qsrc[(size_t)r * N_ + c0 + j];
            kcs[r][j] = ksrc[(size_t)r * N_ + c0 + j];
        }
        __syncthreads();
#pragma unroll 4
        for (int nn = 0; nn < 128; nn++) {
            float q0 = qcs[2 * ddp][nn], q1 = qcs[2 * ddp + 1][nn];
            float k0 = kcs[2 * ep][nn],  k1 = kcs[2 * ep + 1][nn];
            a00 += q0 * k0; a01 += q0 * k1;
            a10 += q1 * k0; a11 += q1 * k1;
        }
        __syncthreads();
    }
    const float* ivq = g_inv + 2048 + bh * 32;
    const float* ivk = g_inv + 4096 + bh * 32;
    float temp = temp_sc[h];
    att[2 * ddp][2 * ep]         = a00 * ivq[2 * ddp]     * ivk[2 * ep]     * temp;
    att[2 * ddp][2 * ep + 1]     = a01 * ivq[2 * ddp]     * ivk[2 * ep + 1] * temp;
    att[2 * ddp + 1][2 * ep]     = a10 * ivq[2 * ddp + 1] * ivk[2 * ep]     * temp;
    att[2 * ddp + 1][2 * ep + 1] = a11 * ivq[2 * ddp + 1] * ivk[2 * ep + 1] * temp;
    __syncthreads();

    // softmax over e: 8 warps, 4 rows each
    int w = tid >> 5, l = tid & 31;
#pragma unroll
    for (int r0 = 0; r0 < 4; r0++) {
        int r = w * 4 + r0;
        float v = att[r][l];
        float m = v;
#pragma unroll
        for (int o = 16; o > 0; o >>= 1) m = fmaxf(m, __shfl_xor_sync(0xffffffffu, m, o));
        float e = __expf(v - m);
        float sum = e;
#pragma unroll
        for (int o = 16; o > 0; o >>= 1) sum += __shfl_xor_sync(0xffffffffu, sum, o);
        g_attn[bh * 1024 + r * 32 + l] = e / sum;
    }
}

// ---------------------------------------------------------------------------
// K6: combine. out[b][c][nn] = (channel attn @ vc)[c][nn] + scrambled x_sa.
// Scrambled x_sa gather done via coalesced SMEM tile (pad 33 -> conflict-free).
//   out coordinate (c = h*32+ddc, nn): x_sa term = g_xsa[b][(nn>>4)&7][nn>>7][(nn&15)*256 + c]
// Block: (ch = nn>>7, bh); threads over 128 nn; 32 c-rows each.
// ---------------------------------------------------------------------------
__global__ __launch_bounds__(128) void k6_combine(float* __restrict__ out) {
    int ch = blockIdx.x;                     // 0..31, == nn>>7 for this block
    int bh = blockIdx.y;
    int b = bh >> 3, h = bh & 7;
    __shared__ float vcs[32][128];
    __shared__ float sas[128][33];
    __shared__ float att[1024];
    int tid = threadIdx.x;                   // 128

    const float* vsrc = g_proj + ((size_t)5 * 2048 + bh * 32) * N_ + ch * 128;  // slab 5 = v_c
#pragma unroll
    for (int i = 0; i < 32; i++) {
        int f = tid + i * 128;
        int e = f >> 7, j = f & 127;
        vcs[e][j] = vsrc[(size_t)e * N_ + j];
    }
#pragma unroll
    for (int i = 0; i < 32; i++) {
        int f = tid + i * 128;
        int tp = f >> 5, dc = f & 31;
        sas[tp][dc] = g_xsa[((size_t)(b * 8 + (tp >> 4)) * 32 + ch) * N_ +
                            (tp & 15) * 256 + h * 32 + dc];
    }
#pragma unroll
    for (int i = 0; i < 8; i++) att[tid + i * 128] = g_attn[bh * 1024 + tid + i * 128];
    __syncthreads();

    float acc[32];
#pragma unroll
    for (int dc = 0; dc < 32; dc++) acc[dc] = 0.f;
#pragma unroll 4
    for (int e = 0; e < 32; e++) {
        float v = vcs[e][tid];
#pragma unroll
        for (int dc = 0; dc < 32; dc++) acc[dc] += att[dc * 32 + e] * v;
    }
    float* ob = out + (size_t)(b * 256 + h * 32) * N_ + ch * 128 + tid;
#pragma unroll
    for (int dc = 0; dc < 32; dc++) ob[(size_t)dc * N_] = acc[dc] + sas[tid][dc];
}

// ---------------------------------------------------------------------------
extern "C" void kernel_launch(void* const* d_in, const int* in_sizes, int n_in,
                              void* d_out, int out_size) {
    const float* x    = (const float*)d_in[0];
    const float* Wsa  = (const float*)d_in[1];
    const float* EF   = (const float*)d_in[2];
    const float* t2sa = (const float*)d_in[3];
    const float* Wsc  = (const float*)d_in[4];
    const float* tsc  = (const float*)d_in[5];
    float* out = (float*)d_out;

    k1_gemm<<<dim3(32, 12, 8), 256>>>(x, Wsa, Wsc);
    k2_norm<<<dim3(2048, 3), 256>>>();
    k3_kvproj<<<dim3(128, 8), 256>>>(EF);
    k3r_reduce<<<1024, 256>>>();
    k4_spatial<<<dim3(16, 64), 256>>>(t2sa);
    k5_gram<<<64, 256>>>(tsc);
    k6_combine<<<dim3(32, 64), 128>>>(out);
}

// round 5
// speedup vs baseline: 1.1979x; 1.1979x over previous
#include <cuda_runtime.h>
#include <cuda_bf16.h>
#include <math.h>
#include <stdint.h>

// Problem constants
#define B_ 8
#define C_ 256
#define N_ 4096
#define H_ 8
#define D_ 32
#define P_ 64

// Scratch (device globals; allocation-free contract)
// g_proj layout: [slab][b][row256][n] where slab = proj*3+comp:
//   0=q_sa, 1=k_sa, 2=v_sa, 3=q_c, 4=k_c, 5=v_c ; row256 = h*32+d
__device__ float g_proj[6u * 8u * 256u * 4096u];      // 201 MB
__device__ float g_inv[3 * 2048];
__device__ float g_kvp[8][2 * 64 * 32 * 64];
__device__ float g_kv[2 * 64 * 32 * 64];
__device__ float g_attn[64 * 32 * 32];
__device__ float g_xsa[8u * 8u * 32u * 4096u];

// bf16 split operands for the tensor-core GEMM
__device__ __nv_bfloat16 g_Whi[1536 * 256];
__device__ __nv_bfloat16 g_Wlo[1536 * 256];
__device__ __nv_bfloat16 g_xhi[8u * 4096u * 256u];   // [b][n][c]  (transposed!)
__device__ __nv_bfloat16 g_xlo[8u * 4096u * 256u];

// ---------------------------------------------------------------------------
// helpers
// ---------------------------------------------------------------------------
__device__ __forceinline__ uint32_t smem_u32(const void* p) {
    uint32_t a;
    asm("{ .reg .u64 t; cvta.to.shared.u64 t, %1; cvt.u32.u64 %0, t; }" : "=r"(a) : "l"(p));
    return a;
}
#define CP_ASYNC16(dst, src) \
    asm volatile("cp.async.cg.shared.global [%0], [%1], 16;" :: "r"(dst), "l"(src))
#define CP_COMMIT() asm volatile("cp.async.commit_group;" ::: "memory")
#define CP_WAIT1()  asm volatile("cp.async.wait_group 1;" ::: "memory")

__device__ __forceinline__ void mma_bf16(float* d, const uint32_t* a, const uint32_t* bb) {
    asm volatile(
        "mma.sync.aligned.m16n8k16.row.col.f32.bf16.bf16.f32 "
        "{%0,%1,%2,%3}, {%4,%5,%6,%7}, {%8,%9}, {%0,%1,%2,%3};"
        : "+f"(d[0]), "+f"(d[1]), "+f"(d[2]), "+f"(d[3])
        : "r"(a[0]), "r"(a[1]), "r"(a[2]), "r"(a[3]), "r"(bb[0]), "r"(bb[1]));
}

// ---------------------------------------------------------------------------
// K0w: pack the 1536 used weight rows into bf16 hi/lo, GEMM row order.
// ---------------------------------------------------------------------------
__global__ __launch_bounds__(256) void k0w_pack(const float* __restrict__ Wsa,
                                                const float* __restrict__ Wsc) {
    int e = blockIdx.x * 256 + threadIdx.x;       // 0 .. 393215
    int r = e >> 8, c = e & 255;
    int p = (r >= 768) ? 1 : 0;
    int rr = r - p * 768;
    int t = rr >> 8;
    const float* Wp = p ? Wsc : Wsa;
    int srow = rr + ((p == 0 && t == 2) ? 256 : 0);
    float v = Wp[(size_t)srow * 256 + c];
    __nv_bfloat16 hi = __float2bfloat16(v);
    float lo = v - __bfloat162float(hi);
    g_Whi[e] = hi;
    g_Wlo[e] = __float2bfloat16(lo);
}

// ---------------------------------------------------------------------------
// K0x: transpose x [b][c][n] -> [b][n][c] with bf16 hi/lo split.
// ---------------------------------------------------------------------------
__global__ __launch_bounds__(128) void k0x_pack(const float* __restrict__ x) {
    int n0 = blockIdx.x * 128;
    int b = blockIdx.y;
    __shared__ float sm[64][132];
    int tid = threadIdx.x;
    const float* xb = x + (size_t)b * C_ * N_;

    for (int c0 = 0; c0 < 256; c0 += 64) {
#pragma unroll
        for (int i = 0; i < 16; i++) {
            int u = tid + i * 128;
            int c = u >> 5, nq = u & 31;
            *(float4*)&sm[c][nq * 4] =
                *(const float4*)(xb + (size_t)(c0 + c) * N_ + n0 + nq * 4);
        }
        __syncthreads();
        // thread tid owns token n = n0+tid; emit 64 contiguous c values
        uint32_t hibuf[32], lobuf[32];
#pragma unroll
        for (int c = 0; c < 64; c += 2) {
            float v0 = sm[c][tid], v1 = sm[c + 1][tid];
            __nv_bfloat16 h0 = __float2bfloat16(v0), h1 = __float2bfloat16(v1);
            __nv_bfloat16 l0 = __float2bfloat16(v0 - __bfloat162float(h0));
            __nv_bfloat16 l1 = __float2bfloat16(v1 - __bfloat162float(h1));
            hibuf[c >> 1] = (uint32_t)__bfloat16_as_ushort(h0) |
                            ((uint32_t)__bfloat16_as_ushort(h1) << 16);
            lobuf[c >> 1] = (uint32_t)__bfloat16_as_ushort(l0) |
                            ((uint32_t)__bfloat16_as_ushort(l1) << 16);
        }
        size_t obase = ((size_t)b * 4096 + n0 + tid) * 256 + c0;
#pragma unroll
        for (int j = 0; j < 8; j++) {
            *(uint4*)&g_xhi[obase + j * 8] = *(uint4*)&hibuf[j * 4];
            *(uint4*)&g_xlo[obase + j * 8] = *(uint4*)&lobuf[j * 4];
        }
        __syncthreads();
    }
}

// ---------------------------------------------------------------------------
// K1: mma.sync bf16-split GEMM.  D[m][n] = sum_c W[m][c] * x[b][c][n]
// CTA tile 128m x 128n; 8 warps (2m x 4n), warp tile 64x32.
// K loop: 3 terms x 16 chunks of k16 = 48 steps, cp.async double buffer.
// ---------------------------------------------------------------------------
__global__ __launch_bounds__(256) void k1_mma() {
    const int n0 = blockIdx.x * 128;
    const int my = blockIdx.y;                  // 0..11
    const int b  = blockIdx.z;
    const int m0 = my * 128;

    __shared__ __nv_bfloat16 sA[2][128][16];
    __shared__ __nv_bfloat16 sB[2][128][16];

    const int tid = threadIdx.x;
    const int wid = tid >> 5, lane = tid & 31;
    const int wm = (wid & 1) * 64, wn = (wid >> 1) * 32;
    const int g = lane >> 2, t4 = lane & 3;

    const __nv_bfloat16* Asrc[3] = { g_Whi, g_Whi, g_Wlo };
    const __nv_bfloat16* Bsrc[3] = { g_xhi, g_xlo, g_xhi };

    float acc[4][4][4];
#pragma unroll
    for (int mt = 0; mt < 4; mt++)
#pragma unroll
        for (int nt = 0; nt < 4; nt++)
#pragma unroll
            for (int j = 0; j < 4; j++) acc[mt][nt][j] = 0.f;

    // cp.async: each thread moves one 16B unit of A and one of B per step
    const int arow = tid >> 1, aseg = tid & 1;
    const uint32_t dA = smem_u32(&sA[0][0][0]) + (uint32_t)(arow * 16 + aseg * 8) * 2;
    const uint32_t dB = smem_u32(&sB[0][0][0]) + (uint32_t)(arow * 16 + aseg * 8) * 2;
    // buffer stride = 128*16*2 = 4096 bytes

#define LOAD_STEP(s, buf)                                                              \
    do {                                                                               \
        int _t = (s) >> 4, _k0 = ((s) & 15) * 16;                                      \
        const __nv_bfloat16* _As = Asrc[_t] + (size_t)(m0 + arow) * 256 + _k0 + aseg * 8; \
        const __nv_bfloat16* _Bs = Bsrc[_t] + ((size_t)b * 4096 + n0 + arow) * 256 + _k0 + aseg * 8; \
        CP_ASYNC16(dA + (buf) * 4096u, _As);                                           \
        CP_ASYNC16(dB + (buf) * 4096u, _Bs);                                           \
    } while (0)

    LOAD_STEP(0, 0); CP_COMMIT();
    LOAD_STEP(1, 1); CP_COMMIT();

    for (int s = 0; s < 48; s++) {
        const int buf = s & 1;
        CP_WAIT1();
        __syncthreads();

        uint32_t af[4][4], bfr[4][2];
#pragma unroll
        for (int mt = 0; mt < 4; mt++) {
            const __nv_bfloat16* base = &sA[buf][wm + mt * 16 + g][0];
            af[mt][0] = *(const uint32_t*)(base + 2 * t4);
            af[mt][1] = *(const uint32_t*)(base + 8 * 16 + 2 * t4);
            af[mt][2] = *(const uint32_t*)(base + 2 * t4 + 8);
            af[mt][3] = *(const uint32_t*)(base + 8 * 16 + 2 * t4 + 8);
        }
#pragma unroll
        for (int nt = 0; nt < 4; nt++) {
            const __nv_bfloat16* nb = &sB[buf][wn + nt * 8 + g][0];
            bfr[nt][0] = *(const uint32_t*)(nb + 2 * t4);
            bfr[nt][1] = *(const uint32_t*)(nb + 2 * t4 + 8);
        }
#pragma unroll
        for (int mt = 0; mt < 4; mt++)
#pragma unroll
            for (int nt = 0; nt < 4; nt++)
                mma_bf16(acc[mt][nt], af[mt], bfr[nt]);

        __syncthreads();
        if (s + 2 < 48) LOAD_STEP(s + 2, buf);
        CP_COMMIT();
    }
#undef LOAD_STEP

    // epilogue -> g_proj
    const int slab = my >> 1;
    const int rb = (my & 1) * 128;
#pragma unroll
    for (int mt = 0; mt < 4; mt++) {
        int r0 = rb + wm + mt * 16 + g;
        float* p0 = g_proj + (((size_t)slab * 8 + b) * 256 + r0) * (size_t)N_ + n0 + wn;
        float* p1 = p0 + 8 * (size_t)N_;
#pragma unroll
        for (int nt = 0; nt < 4; nt++) {
            *(float2*)(p0 + nt * 8 + 2 * t4) = make_float2(acc[mt][nt][0], acc[mt][nt][1]);
            *(float2*)(p1 + nt * 8 + 2 * t4) = make_float2(acc[mt][nt][2], acc[mt][nt][3]);
        }
    }
}

// ---------------------------------------------------------------------------
// K2: row L2 norms over N for q_sa (slab 0), q_c (slab 3), k_c (slab 4)
// ---------------------------------------------------------------------------
__global__ __launch_bounds__(256) void k2_norm() {
    int which = blockIdx.y;
    int row = blockIdx.x;
    int slab = (which == 0) ? 0 : (which == 1 ? 3 : 4);
    const float* src = g_proj + ((size_t)slab * 2048 + row) * N_;
    int tid = threadIdx.x;
    float s = 0.f;
    for (int i = tid; i < N_; i += 256) { float v = src[i]; s += v * v; }
    __shared__ float red[8];
#pragma unroll
    for (int o = 16; o > 0; o >>= 1) s += __shfl_down_sync(0xffffffffu, s, o);
    if ((tid & 31) == 0) red[tid >> 5] = s;
    __syncthreads();
    if (tid < 8) {
        s = red[tid];
#pragma unroll
        for (int o = 4; o > 0; o >>= 1) s += __shfl_down_sync(0xffu, s, o);
        if (tid == 0) g_inv[which * 2048 + row] = 1.f / fmaxf(sqrtf(s), 1e-12f);
    }
}

// ---------------------------------------------------------------------------
// K3: Linformer projection: g_kv[s][bh][d][p] = sum_n T[s][bh][d][n] * EF[n][p]
// ---------------------------------------------------------------------------
__global__ __launch_bounds__(256) void k3_kvproj(const float* __restrict__ EF) {
    int s  = blockIdx.x >> 6;
    int bh = blockIdx.x & 63;
    int sp = blockIdx.y;
    const float* src = g_proj + ((size_t)(1 + s) * 2048 + bh * 32) * N_;
    __shared__ float EFs[64][64];
    __shared__ float Xs[32][65];
    int tid = threadIdx.x;
    int dd = tid & 31, pg = tid >> 5;
    float acc[8];
#pragma unroll
    for (int j = 0; j < 8; j++) acc[j] = 0.f;

    for (int c = 0; c < 8; c++) {
        int nb = sp * 512 + c * 64;
#pragma unroll
        for (int i = 0; i < 4; i++) {
            int f = tid + i * 256;
            int nn = f >> 4, pq = f & 15;
            *(float4*)&EFs[nn][pq * 4] = *(const float4*)(EF + (size_t)(nb + nn) * 64 + pq * 4);
        }
#pragma unroll
        for (int i = 0; i < 8; i++) {
            int f = tid + i * 256;
            int r = f >> 6, j = f & 63;
            Xs[r][j] = src[(size_t)r * N_ + nb + j];
        }
        __syncthreads();
#pragma unroll 4
        for (int nn = 0; nn < 64; nn++) {
            float xv = Xs[dd][nn];
            float4 e0 = *(const float4*)&EFs[nn][pg * 8];
            float4 e1 = *(const float4*)&EFs[nn][pg * 8 + 4];
            acc[0] += xv * e0.x; acc[1] += xv * e0.y;
            acc[2] += xv * e0.z; acc[3] += xv * e0.w;
            acc[4] += xv * e1.x; acc[5] += xv * e1.y;
            acc[6] += xv * e1.z; acc[7] += xv * e1.w;
        }
        __syncthreads();
    }
    float* o = &g_kvp[sp][((s * 64 + bh) * 32 + dd) * 64 + pg * 8];
    *(float4*)&o[0] = make_float4(acc[0], acc[1], acc[2], acc[3]);
    *(float4*)&o[4] = make_float4(acc[4], acc[5], acc[6], acc[7]);
}

__global__ __launch_bounds__(256) void k3r_reduce() {
    int i = blockIdx.x * 256 + threadIdx.x;
    float s = 0.f;
#pragma unroll
    for (int sp = 0; sp < 8; sp++) s += g_kvp[sp][i];
    g_kv[i] = s;
}

// ---------------------------------------------------------------------------
// K4: spatial attention
// ---------------------------------------------------------------------------
__global__ __launch_bounds__(256) void k4_spatial(const float* __restrict__ temp2_sa) {
    int ch = blockIdx.x, bh = blockIdx.y;
    int h = bh & 7;
    __shared__ float Ks[32][64], Vs[32][64];
    int tid = threadIdx.x;
    float* ksf = &Ks[0][0];
    float* vsf = &Vs[0][0];
    for (int i = tid; i < 2048; i += 256) {
        ksf[i] = g_kv[(0 * 64 + bh) * 2048 + i];
        vsf[i] = g_kv[(1 * 64 + bh) * 2048 + i];
    }
    __syncthreads();

    int n = ch * 256 + tid;
    const float* qb = g_proj + (size_t)(bh * 32) * N_ + n;
    const float* iv = g_inv + bh * 32;
    float temp = temp2_sa[h];

    float qn[32];
#pragma unroll
    for (int d = 0; d < 32; d++) qn[d] = qb[(size_t)d * N_] * iv[d];

    float s[64];
#pragma unroll
    for (int j = 0; j < 64; j++) s[j] = 0.f;
#pragma unroll
    for (int d = 0; d < 32; d++) {
        float q = qn[d];
#pragma unroll
        for (int pq = 0; pq < 16; pq++) {
            float4 k4 = *(const float4*)&Ks[d][pq * 4];
            s[pq * 4 + 0] += q * k4.x;
            s[pq * 4 + 1] += q * k4.y;
            s[pq * 4 + 2] += q * k4.z;
            s[pq * 4 + 3] += q * k4.w;
        }
    }
    float mx = -1e30f;
#pragma unroll
    for (int j = 0; j < 64; j++) { s[j] *= temp; mx = fmaxf(mx, s[j]); }
    float sum = 0.f;
#pragma unroll
    for (int j = 0; j < 64; j++) { float e = __expf(s[j] - mx); s[j] = e; sum += e; }
    float isum = 1.f / sum;

    float* ob = g_xsa + (size_t)(bh * 32) * N_ + n;
#pragma unroll
    for (int d = 0; d < 32; d++) {
        float o = 0.f;
#pragma unroll
        for (int pq = 0; pq < 16; pq++) {
            float4 v4 = *(const float4*)&Vs[d][pq * 4];
            o += s[pq * 4 + 0] * v4.x + s[pq * 4 + 1] * v4.y +
                 s[pq * 4 + 2] * v4.z + s[pq * 4 + 3] * v4.w;
        }
        ob[(size_t)d * N_] = o * isum;
    }
}

// ---------------------------------------------------------------------------
// K5: channel gram + softmax
// ---------------------------------------------------------------------------
__global__ __launch_bounds__(256) void k5_gram(const float* __restrict__ temp_sc) {
    int bh = blockIdx.x;
    int h = bh & 7;
    __shared__ float qcs[32][133], kcs[32][133];
    __shared__ float att[32][33];
    int tid = threadIdx.x;
    int ddp = tid >> 4, ep = tid & 15;
    float a00 = 0.f, a01 = 0.f, a10 = 0.f, a11 = 0.f;
    const float* qsrc = g_proj + ((size_t)3 * 2048 + bh * 32) * N_;
    const float* ksrc = g_proj + ((size_t)4 * 2048 + bh * 32) * N_;

    for (int c0 = 0; c0 < N_; c0 += 128) {
#pragma unroll
        for (int i = 0; i < 16; i++) {
            int f = tid + i * 256;
            int r = f >> 7, j = f & 127;
            qcs[r][j] = qsrc[(size_t)r * N_ + c0 + j];
            kcs[r][j] = ksrc[(size_t)r * N_ + c0 + j];
        }
        __syncthreads();
#pragma unroll 4
        for (int nn = 0; nn < 128; nn++) {
            float q0 = qcs[2 * ddp][nn], q1 = qcs[2 * ddp + 1][nn];
            float k0 = kcs[2 * ep][nn],  k1 = kcs[2 * ep + 1][nn];
            a00 += q0 * k0; a01 += q0 * k1;
            a10 += q1 * k0; a11 += q1 * k1;
        }
        __syncthreads();
    }
    const float* ivq = g_inv + 2048 + bh * 32;
    const float* ivk = g_inv + 4096 + bh * 32;
    float temp = temp_sc[h];
    att[2 * ddp][2 * ep]         = a00 * ivq[2 * ddp]     * ivk[2 * ep]     * temp;
    att[2 * ddp][2 * ep + 1]     = a01 * ivq[2 * ddp]     * ivk[2 * ep + 1] * temp;
    att[2 * ddp + 1][2 * ep]     = a10 * ivq[2 * ddp + 1] * ivk[2 * ep]     * temp;
    att[2 * ddp + 1][2 * ep + 1] = a11 * ivq[2 * ddp + 1] * ivk[2 * ep + 1] * temp;
    __syncthreads();

    int w = tid >> 5, l = tid & 31;
#pragma unroll
    for (int r0 = 0; r0 < 4; r0++) {
        int r = w * 4 + r0;
        float v = att[r][l];
        float m = v;
#pragma unroll
        for (int o = 16; o > 0; o >>= 1) m = fmaxf(m, __shfl_xor_sync(0xffffffffu, m, o));
        float e = __expf(v - m);
        float sum = e;
#pragma unroll
        for (int o = 16; o > 0; o >>= 1) sum += __shfl_xor_sync(0xffffffffu, sum, o);
        g_attn[bh * 1024 + r * 32 + l] = e / sum;
    }
}

// ---------------------------------------------------------------------------
// K6: combine
// ---------------------------------------------------------------------------
__global__ __launch_bounds__(128) void k6_combine(float* __restrict__ out) {
    int ch = blockIdx.x;
    int bh = blockIdx.y;
    int b = bh >> 3, h = bh & 7;
    __shared__ float vcs[32][128];
    __shared__ float sas[128][33];
    __shared__ float att[1024];
    int tid = threadIdx.x;

    const float* vsrc = g_proj + ((size_t)5 * 2048 + bh * 32) * N_ + ch * 128;
#pragma unroll
    for (int i = 0; i < 32; i++) {
        int f = tid + i * 128;
        int e = f >> 7, j = f & 127;
        vcs[e][j] = vsrc[(size_t)e * N_ + j];
    }
#pragma unroll
    for (int i = 0; i < 32; i++) {
        int f = tid + i * 128;
        int tp = f >> 5, dc = f & 31;
        sas[tp][dc] = g_xsa[((size_t)(b * 8 + (tp >> 4)) * 32 + ch) * N_ +
                            (tp & 15) * 256 + h * 32 + dc];
    }
#pragma unroll
    for (int i = 0; i < 8; i++) att[tid + i * 128] = g_attn[bh * 1024 + tid + i * 128];
    __syncthreads();

    float acc[32];
#pragma unroll
    for (int dc = 0; dc < 32; dc++) acc[dc] = 0.f;
#pragma unroll 4
    for (int e = 0; e < 32; e++) {
        float v = vcs[e][tid];
#pragma unroll
        for (int dc = 0; dc < 32; dc++) acc[dc] += att[dc * 32 + e] * v;
    }
    float* ob = out + (size_t)(b * 256 + h * 32) * N_ + ch * 128 + tid;
#pragma unroll
    for (int dc = 0; dc < 32; dc++) ob[(size_t)dc * N_] = acc[dc] + sas[tid][dc];
}

// ---------------------------------------------------------------------------
extern "C" void kernel_launch(void* const* d_in, const int* in_sizes, int n_in,
                              void* d_out, int out_size) {
    const float* x    = (const float*)d_in[0];
    const float* Wsa  = (const float*)d_in[1];
    const float* EF   = (const float*)d_in[2];
    const float* t2sa = (const float*)d_in[3];
    const float* Wsc  = (const float*)d_in[4];
    const float* tsc  = (const float*)d_in[5];
    float* out = (float*)d_out;

    k0w_pack<<<1536, 256>>>(Wsa, Wsc);
    k0x_pack<<<dim3(32, 8), 128>>>(x);
    k1_mma<<<dim3(32, 12, 8), 256>>>();
    k2_norm<<<dim3(2048, 3), 256>>>();
    k3_kvproj<<<dim3(128, 8), 256>>>(EF);
    k3r_reduce<<<1024, 256>>>();
    k4_spatial<<<dim3(16, 64), 256>>>(t2sa);
    k5_gram<<<64, 256>>>(tsc);
    k6_combine<<<dim3(32, 64), 128>>>(out);
}

// round 6
// speedup vs baseline: 1.4334x; 1.1966x over previous
#include <cuda_runtime.h>
#include <cuda_bf16.h>
#include <cuda_fp16.h>
#include <math.h>
#include <stdint.h>

// Problem constants
#define B_ 8
#define C_ 256
#define N_ 4096
#define H_ 8
#define D_ 32
#define P_ 64

// Scratch (device globals; allocation-free contract)
// g_proj layout: [slab][b][row256][n] (fp16), slab: 0=q_sa,1=k_sa,2=v_sa,3=q_c,4=k_c,5=v_c
__device__ __half g_proj[6u * 8u * 256u * 4096u];     // 100 MB
__device__ float g_sumsq[3 * 2048];                   // partial sum-of-squares (atomic)
__device__ float g_inv[3 * 2048];                     // 1/max(||row||,eps)
__device__ float g_kvp[8][2 * 64 * 32 * 64];
__device__ float g_kv[2 * 64 * 32 * 64];
__device__ float g_attn[64 * 32 * 32];
__device__ __half g_xsa[8u * 8u * 32u * 4096u];       // spatial out [b][h][d][n], fp16

// bf16 split operands for the tensor-core GEMM
__device__ __nv_bfloat16 g_Whi[1536 * 256];
__device__ __nv_bfloat16 g_Wlo[1536 * 256];
__device__ __nv_bfloat16 g_xhi[8u * 4096u * 256u];    // [b][n][c]  (transposed)
__device__ __nv_bfloat16 g_xlo[8u * 4096u * 256u];

// ---------------------------------------------------------------------------
// helpers
// ---------------------------------------------------------------------------
__device__ __forceinline__ uint32_t smem_u32(const void* p) {
    uint32_t a;
    asm("{ .reg .u64 t; cvta.to.shared.u64 t, %1; cvt.u32.u64 %0, t; }" : "=r"(a) : "l"(p));
    return a;
}
#define CP_ASYNC16(dst, src) \
    asm volatile("cp.async.cg.shared.global [%0], [%1], 16;" :: "r"(dst), "l"(src))
#define CP_COMMIT() asm volatile("cp.async.commit_group;" ::: "memory")
#define CP_WAIT1()  asm volatile("cp.async.wait_group 1;" ::: "memory")

__device__ __forceinline__ void mma_bf16(float* d, const uint32_t* a, const uint32_t* bb) {
    asm volatile(
        "mma.sync.aligned.m16n8k16.row.col.f32.bf16.bf16.f32 "
        "{%0,%1,%2,%3}, {%4,%5,%6,%7}, {%8,%9}, {%0,%1,%2,%3};"
        : "+f"(d[0]), "+f"(d[1]), "+f"(d[2]), "+f"(d[3])
        : "r"(a[0]), "r"(a[1]), "r"(a[2]), "r"(a[3]), "r"(bb[0]), "r"(bb[1]));
}

// ---------------------------------------------------------------------------
// K0w: pack weights into bf16 hi/lo (GEMM row order) + zero g_sumsq.
// ---------------------------------------------------------------------------
__global__ __launch_bounds__(256) void k0w_pack(const float* __restrict__ Wsa,
                                                const float* __restrict__ Wsc) {
    int e = blockIdx.x * 256 + threadIdx.x;       // 0 .. 393215
    if (e < 3 * 2048) g_sumsq[e] = 0.f;
    int r = e >> 8, c = e & 255;
    int p = (r >= 768) ? 1 : 0;
    int rr = r - p * 768;
    int t = rr >> 8;
    const float* Wp = p ? Wsc : Wsa;
    int srow = rr + ((p == 0 && t == 2) ? 256 : 0);
    float v = Wp[(size_t)srow * 256 + c];
    __nv_bfloat16 hi = __float2bfloat16(v);
    float lo = v - __bfloat162float(hi);
    g_Whi[e] = hi;
    g_Wlo[e] = __float2bfloat16(lo);
}

// ---------------------------------------------------------------------------
// K0x: transpose x [b][c][n] -> [b][n][c] with bf16 hi/lo split.
// ---------------------------------------------------------------------------
__global__ __launch_bounds__(128) void k0x_pack(const float* __restrict__ x) {
    int n0 = blockIdx.x * 128;
    int b = blockIdx.y;
    __shared__ float sm[64][132];
    int tid = threadIdx.x;
    const float* xb = x + (size_t)b * C_ * N_;

    for (int c0 = 0; c0 < 256; c0 += 64) {
#pragma unroll
        for (int i = 0; i < 16; i++) {
            int u = tid + i * 128;
            int c = u >> 5, nq = u & 31;
            *(float4*)&sm[c][nq * 4] =
                *(const float4*)(xb + (size_t)(c0 + c) * N_ + n0 + nq * 4);
        }
        __syncthreads();
        uint32_t hibuf[32], lobuf[32];
#pragma unroll
        for (int c = 0; c < 64; c += 2) {
            float v0 = sm[c][tid], v1 = sm[c + 1][tid];
            __nv_bfloat16 h0 = __float2bfloat16(v0), h1 = __float2bfloat16(v1);
            __nv_bfloat16 l0 = __float2bfloat16(v0 - __bfloat162float(h0));
            __nv_bfloat16 l1 = __float2bfloat16(v1 - __bfloat162float(h1));
            hibuf[c >> 1] = (uint32_t)__bfloat16_as_ushort(h0) |
                            ((uint32_t)__bfloat16_as_ushort(h1) << 16);
            lobuf[c >> 1] = (uint32_t)__bfloat16_as_ushort(l0) |
                            ((uint32_t)__bfloat16_as_ushort(l1) << 16);
        }
        size_t obase = ((size_t)b * 4096 + n0 + tid) * 256 + c0;
#pragma unroll
        for (int j = 0; j < 8; j++) {
            *(uint4*)&g_xhi[obase + j * 8] = *(uint4*)&hibuf[j * 4];
            *(uint4*)&g_xlo[obase + j * 8] = *(uint4*)&lobuf[j * 4];
        }
        __syncthreads();
    }
}

// ---------------------------------------------------------------------------
// K1: mma.sync bf16-split GEMM + fused row sum-of-squares.
// CTA 128m x 128n; 8 warps (2m x 4n), warp tile 64x32.
// K loop: 3 terms x 8 chunks of k32 = 24 steps, cp.async double buffer.
// smem row stride 40 halves -> conflict-free fragment LDS.
// ---------------------------------------------------------------------------
__global__ __launch_bounds__(256) void k1_mma() {
    const int n0 = blockIdx.x * 128;
    const int my = blockIdx.y;                  // 0..11
    const int b  = blockIdx.z;
    const int m0 = my * 128;

    __shared__ __half sA[2][128][40];
    __shared__ __half sB[2][128][40];

    const int tid = threadIdx.x;
    const int wid = tid >> 5, lane = tid & 31;
    const int wm = (wid & 1) * 64, wn = (wid >> 1) * 32;
    const int g = lane >> 2, t4 = lane & 3;

    const __nv_bfloat16* Asrc[3] = { g_Whi, g_Whi, g_Wlo };
    const __nv_bfloat16* Bsrc[3] = { g_xhi, g_xlo, g_xhi };

    float acc[4][4][4];
#pragma unroll
    for (int mt = 0; mt < 4; mt++)
#pragma unroll
        for (int nt = 0; nt < 4; nt++)
#pragma unroll
            for (int j = 0; j < 4; j++) acc[mt][nt][j] = 0.f;

    // cp.async: each thread moves two 16B units per operand per step
    const int r0u = tid >> 2, s0u = tid & 3;          // unit u = tid
    const int r1u = (tid + 256) >> 2, s1u = tid & 3;  // unit u = tid + 256

#define LOAD_STEP(s, buf)                                                                 \
    do {                                                                                  \
        int _t = (s) / 8, _k0 = ((s) & 7) * 32;                                           \
        const __nv_bfloat16* _A = Asrc[_t] + (size_t)m0 * 256 + _k0;                      \
        const __nv_bfloat16* _B = Bsrc[_t] + ((size_t)b * 4096 + n0) * 256 + _k0;         \
        CP_ASYNC16(smem_u32(&sA[buf][r0u][s0u * 8]), _A + (size_t)r0u * 256 + s0u * 8);   \
        CP_ASYNC16(smem_u32(&sA[buf][r1u][s1u * 8]), _A + (size_t)r1u * 256 + s1u * 8);   \
        CP_ASYNC16(smem_u32(&sB[buf][r0u][s0u * 8]), _B + (size_t)r0u * 256 + s0u * 8);   \
        CP_ASYNC16(smem_u32(&sB[buf][r1u][s1u * 8]), _B + (size_t)r1u * 256 + s1u * 8);   \
    } while (0)

    LOAD_STEP(0, 0); CP_COMMIT();
    LOAD_STEP(1, 1); CP_COMMIT();

    for (int s = 0; s < 24; s++) {
        const int buf = s & 1;
        CP_WAIT1();
        __syncthreads();

#pragma unroll
        for (int h = 0; h < 2; h++) {
            uint32_t af[4][4], bfr[4][2];
#pragma unroll
            for (int mt = 0; mt < 4; mt++) {
                const __half* base = &sA[buf][wm + mt * 16 + g][h * 16];
                af[mt][0] = *(const uint32_t*)(base + 2 * t4);
                af[mt][1] = *(const uint32_t*)(base + 8 * 40 + 2 * t4);
                af[mt][2] = *(const uint32_t*)(base + 2 * t4 + 8);
                af[mt][3] = *(const uint32_t*)(base + 8 * 40 + 2 * t4 + 8);
            }
#pragma unroll
            for (int nt = 0; nt < 4; nt++) {
                const __half* nb = &sB[buf][wn + nt * 8 + g][h * 16];
                bfr[nt][0] = *(const uint32_t*)(nb + 2 * t4);
                bfr[nt][1] = *(const uint32_t*)(nb + 2 * t4 + 8);
            }
#pragma unroll
            for (int mt = 0; mt < 4; mt++)
#pragma unroll
                for (int nt = 0; nt < 4; nt++)
                    mma_bf16(acc[mt][nt], af[mt], bfr[nt]);
        }

        __syncthreads();
        if (s + 2 < 24) LOAD_STEP(s + 2, buf);
        CP_COMMIT();
    }
#undef LOAD_STEP

    // epilogue -> g_proj (fp16) + fused sumsq for slabs 0,3,4
    const int slab = my >> 1;
    const int rb = (my & 1) * 128;
    const int which = (slab == 0) ? 0 : (slab == 3 ? 1 : (slab == 4 ? 2 : -1));
#pragma unroll
    for (int mt = 0; mt < 4; mt++) {
        int r0 = rb + wm + mt * 16 + g;
        __half* p0 = g_proj + (((size_t)slab * 8 + b) * 256 + r0) * (size_t)N_ + n0 + wn;
        __half* p1 = p0 + 8 * (size_t)N_;
        float ss0 = 0.f, ss1 = 0.f;
#pragma unroll
        for (int nt = 0; nt < 4; nt++) {
            float a0 = acc[mt][nt][0], a1 = acc[mt][nt][1];
            float a2 = acc[mt][nt][2], a3 = acc[mt][nt][3];
            *(__half2*)(p0 + nt * 8 + 2 * t4) = __floats2half2_rn(a0, a1);
            *(__half2*)(p1 + nt * 8 + 2 * t4) = __floats2half2_rn(a2, a3);
            ss0 += a0 * a0 + a1 * a1;
            ss1 += a2 * a2 + a3 * a3;
        }
        if (which >= 0) {
            // reduce over the 4 lanes of the quad (t4)
            ss0 += __shfl_xor_sync(0xffffffffu, ss0, 1);
            ss0 += __shfl_xor_sync(0xffffffffu, ss0, 2);
            ss1 += __shfl_xor_sync(0xffffffffu, ss1, 1);
            ss1 += __shfl_xor_sync(0xffffffffu, ss1, 2);
            if (t4 == 0) {
                int row = b * 256 + r0;
                atomicAdd(&g_sumsq[which * 2048 + row], ss0);
                atomicAdd(&g_sumsq[which * 2048 + row + 8], ss1);
            }
        }
    }
}

// ---------------------------------------------------------------------------
// K1n: finalize inverse norms
// ---------------------------------------------------------------------------
__global__ __launch_bounds__(256) void k1n_inv() {
    int i = blockIdx.x * 256 + threadIdx.x;      // 6144
    g_inv[i] = 1.f / fmaxf(sqrtf(g_sumsq[i]), 1e-12f);
}

// ---------------------------------------------------------------------------
// K3: Linformer projection: g_kv[s][bh][d][p] = sum_n T[s][bh][d][n] * EF[n][p]
// ---------------------------------------------------------------------------
__global__ __launch_bounds__(256) void k3_kvproj(const float* __restrict__ EF) {
    int s  = blockIdx.x >> 6;
    int bh = blockIdx.x & 63;
    int sp = blockIdx.y;
    const __half* src = g_proj + ((size_t)(1 + s) * 2048 + bh * 32) * N_;
    __shared__ float EFs[64][64];
    __shared__ float Xs[32][65];
    int tid = threadIdx.x;
    int dd = tid & 31, pg = tid >> 5;
    float acc[8];
#pragma unroll
    for (int j = 0; j < 8; j++) acc[j] = 0.f;

    for (int c = 0; c < 8; c++) {
        int nb = sp * 512 + c * 64;
#pragma unroll
        for (int i = 0; i < 4; i++) {
            int f = tid + i * 256;
            int nn = f >> 4, pq = f & 15;
            *(float4*)&EFs[nn][pq * 4] = *(const float4*)(EF + (size_t)(nb + nn) * 64 + pq * 4);
        }
#pragma unroll
        for (int i = 0; i < 8; i++) {
            int f = tid + i * 256;
            int r = f >> 6, j = f & 63;
            Xs[r][j] = __half2float(src[(size_t)r * N_ + nb + j]);
        }
        __syncthreads();
#pragma unroll 4
        for (int nn = 0; nn < 64; nn++) {
            float xv = Xs[dd][nn];
            float4 e0 = *(const float4*)&EFs[nn][pg * 8];
            float4 e1 = *(const float4*)&EFs[nn][pg * 8 + 4];
            acc[0] += xv * e0.x; acc[1] += xv * e0.y;
            acc[2] += xv * e0.z; acc[3] += xv * e0.w;
            acc[4] += xv * e1.x; acc[5] += xv * e1.y;
            acc[6] += xv * e1.z; acc[7] += xv * e1.w;
        }
        __syncthreads();
    }
    float* o = &g_kvp[sp][((s * 64 + bh) * 32 + dd) * 64 + pg * 8];
    *(float4*)&o[0] = make_float4(acc[0], acc[1], acc[2], acc[3]);
    *(float4*)&o[4] = make_float4(acc[4], acc[5], acc[6], acc[7]);
}

__global__ __launch_bounds__(256) void k3r_reduce() {
    int i = blockIdx.x * 256 + threadIdx.x;
    float s = 0.f;
#pragma unroll
    for (int sp = 0; sp < 8; sp++) s += g_kvp[sp][i];
    g_kv[i] = s;
}

// ---------------------------------------------------------------------------
// K4: spatial attention
// ---------------------------------------------------------------------------
__global__ __launch_bounds__(256) void k4_spatial(const float* __restrict__ temp2_sa) {
    int ch = blockIdx.x, bh = blockIdx.y;
    int h = bh & 7;
    __shared__ float Ks[32][64], Vs[32][64];
    int tid = threadIdx.x;
    float* ksf = &Ks[0][0];
    float* vsf = &Vs[0][0];
    for (int i = tid; i < 2048; i += 256) {
        ksf[i] = g_kv[(0 * 64 + bh) * 2048 + i];
        vsf[i] = g_kv[(1 * 64 + bh) * 2048 + i];
    }
    __syncthreads();

    int n = ch * 256 + tid;
    const __half* qb = g_proj + (size_t)(bh * 32) * N_ + n;
    const float* iv = g_inv + bh * 32;
    float temp = temp2_sa[h];

    float qn[32];
#pragma unroll
    for (int d = 0; d < 32; d++) qn[d] = __half2float(qb[(size_t)d * N_]) * iv[d];

    float s[64];
#pragma unroll
    for (int j = 0; j < 64; j++) s[j] = 0.f;
#pragma unroll
    for (int d = 0; d < 32; d++) {
        float q = qn[d];
#pragma unroll
        for (int pq = 0; pq < 16; pq++) {
            float4 k4 = *(const float4*)&Ks[d][pq * 4];
            s[pq * 4 + 0] += q * k4.x;
            s[pq * 4 + 1] += q * k4.y;
            s[pq * 4 + 2] += q * k4.z;
            s[pq * 4 + 3] += q * k4.w;
        }
    }
    float mx = -1e30f;
#pragma unroll
    for (int j = 0; j < 64; j++) { s[j] *= temp; mx = fmaxf(mx, s[j]); }
    float sum = 0.f;
#pragma unroll
    for (int j = 0; j < 64; j++) { float e = __expf(s[j] - mx); s[j] = e; sum += e; }
    float isum = 1.f / sum;

    __half* ob = g_xsa + (size_t)(bh * 32) * N_ + n;
#pragma unroll
    for (int d = 0; d < 32; d++) {
        float o = 0.f;
#pragma unroll
        for (int pq = 0; pq < 16; pq++) {
            float4 v4 = *(const float4*)&Vs[d][pq * 4];
            o += s[pq * 4 + 0] * v4.x + s[pq * 4 + 1] * v4.y +
                 s[pq * 4 + 2] * v4.z + s[pq * 4 + 3] * v4.w;
        }
        ob[(size_t)d * N_] = __float2half(o * isum);
    }
}

// ---------------------------------------------------------------------------
// K5: channel gram + softmax
// ---------------------------------------------------------------------------
__global__ __launch_bounds__(256) void k5_gram(const float* __restrict__ temp_sc) {
    int bh = blockIdx.x;
    int h = bh & 7;
    __shared__ float qcs[32][133], kcs[32][133];
    __shared__ float att[32][33];
    int tid = threadIdx.x;
    int ddp = tid >> 4, ep = tid & 15;
    float a00 = 0.f, a01 = 0.f, a10 = 0.f, a11 = 0.f;
    const __half* qsrc = g_proj + ((size_t)3 * 2048 + bh * 32) * N_;
    const __half* ksrc = g_proj + ((size_t)4 * 2048 + bh * 32) * N_;

    for (int c0 = 0; c0 < N_; c0 += 128) {
#pragma unroll
        for (int i = 0; i < 16; i++) {
            int f = tid + i * 256;
            int r = f >> 7, j = f & 127;
            qcs[r][j] = __half2float(qsrc[(size_t)r * N_ + c0 + j]);
            kcs[r][j] = __half2float(ksrc[(size_t)r * N_ + c0 + j]);
        }
        __syncthreads();
#pragma unroll 4
        for (int nn = 0; nn < 128; nn++) {
            float q0 = qcs[2 * ddp][nn], q1 = qcs[2 * ddp + 1][nn];
            float k0 = kcs[2 * ep][nn],  k1 = kcs[2 * ep + 1][nn];
            a00 += q0 * k0; a01 += q0 * k1;
            a10 += q1 * k0; a11 += q1 * k1;
        }
        __syncthreads();
    }
    const float* ivq = g_inv + 2048 + bh * 32;
    const float* ivk = g_inv + 4096 + bh * 32;
    float temp = temp_sc[h];
    att[2 * ddp][2 * ep]         = a00 * ivq[2 * ddp]     * ivk[2 * ep]     * temp;
    att[2 * ddp][2 * ep + 1]     = a01 * ivq[2 * ddp]     * ivk[2 * ep + 1] * temp;
    att[2 * ddp + 1][2 * ep]     = a10 * ivq[2 * ddp + 1] * ivk[2 * ep]     * temp;
    att[2 * ddp + 1][2 * ep + 1] = a11 * ivq[2 * ddp + 1] * ivk[2 * ep + 1] * temp;
    __syncthreads();

    int w = tid >> 5, l = tid & 31;
#pragma unroll
    for (int r0 = 0; r0 < 4; r0++) {
        int r = w * 4 + r0;
        float v = att[r][l];
        float m = v;
#pragma unroll
        for (int o = 16; o > 0; o >>= 1) m = fmaxf(m, __shfl_xor_sync(0xffffffffu, m, o));
        float e = __expf(v - m);
        float sum = e;
#pragma unroll
        for (int o = 16; o > 0; o >>= 1) sum += __shfl_xor_sync(0xffffffffu, sum, o);
        g_attn[bh * 1024 + r * 32 + l] = e / sum;
    }
}

// ---------------------------------------------------------------------------
// K6: combine
// ---------------------------------------------------------------------------
__global__ __launch_bounds__(128) void k6_combine(float* __restrict__ out) {
    int ch = blockIdx.x;
    int bh = blockIdx.y;
    int b = bh >> 3, h = bh & 7;
    __shared__ float vcs[32][128];
    __shared__ float sas[128][33];
    __shared__ float att[1024];
    int tid = threadIdx.x;

    const __half* vsrc = g_proj + ((size_t)5 * 2048 + bh * 32) * N_ + ch * 128;
#pragma unroll
    for (int i = 0; i < 32; i++) {
        int f = tid + i * 128;
        int e = f >> 7, j = f & 127;
        vcs[e][j] = __half2float(vsrc[(size_t)e * N_ + j]);
    }
#pragma unroll
    for (int i = 0; i < 32; i++) {
        int f = tid + i * 128;
        int tp = f >> 5, dc = f & 31;
        sas[tp][dc] = __half2float(g_xsa[((size_t)(b * 8 + (tp >> 4)) * 32 + ch) * N_ +
                                         (tp & 15) * 256 + h * 32 + dc]);
    }
#pragma unroll
    for (int i = 0; i < 8; i++) att[tid + i * 128] = g_attn[bh * 1024 + tid + i * 128];
    __syncthreads();

    float acc[32];
#pragma unroll
    for (int dc = 0; dc < 32; dc++) acc[dc] = 0.f;
#pragma unroll 4
    for (int e = 0; e < 32; e++) {
        float v = vcs[e][tid];
#pragma unroll
        for (int dc = 0; dc < 32; dc++) acc[dc] += att[dc * 32 + e] * v;
    }
    float* ob = out + (size_t)(b * 256 + h * 32) * N_ + ch * 128 + tid;
#pragma unroll
    for (int dc = 0; dc < 32; dc++) ob[(size_t)dc * N_] = acc[dc] + sas[tid][dc];
}

// ---------------------------------------------------------------------------
extern "C" void kernel_launch(void* const* d_in, const int* in_sizes, int n_in,
                              void* d_out, int out_size) {
    const float* x    = (const float*)d_in[0];
    const float* Wsa  = (const float*)d_in[1];
    const float* EF   = (const float*)d_in[2];
    const float* t2sa = (const float*)d_in[3];
    const float* Wsc  = (const float*)d_in[4];
    const float* tsc  = (const float*)d_in[5];
    float* out = (float*)d_out;

    k0w_pack<<<1536, 256>>>(Wsa, Wsc);
    k0x_pack<<<dim3(32, 8), 128>>>(x);
    k1_mma<<<dim3(32, 12, 8), 256>>>();
    k1n_inv<<<24, 256>>>();
    k3_kvproj<<<dim3(128, 8), 256>>>(EF);
    k3r_reduce<<<1024, 256>>>();
    k4_spatial<<<dim3(16, 64), 256>>>(t2sa);
    k5_gram<<<64, 256>>>(tsc);
    k6_combine<<<dim3(32, 64), 128>>>(out);
}

// round 8
// speedup vs baseline: 1.5133x; 1.0557x over previous
#include <cuda_runtime.h>
#include <cuda_bf16.h>
#include <cuda_fp16.h>
#include <math.h>
#include <stdint.h>

// Problem constants
#define B_ 8
#define C_ 256
#define N_ 4096
#define H_ 8
#define D_ 32
#define P_ 64

// Scratch (device globals; allocation-free contract)
// g_proj layout: [slab][b][row256][n] (fp16), slab: 0=q_sa,1=k_sa,2=v_sa,3=q_c,4=k_c,5=v_c
__device__ __half g_proj[6u * 8u * 256u * 4096u];     // 100 MB
__device__ float g_sumsq[3 * 2048];                   // partial sum-of-squares (atomic)
__device__ float g_inv[3 * 2048];                     // 1/max(||row||,eps)
__device__ float g_kvp[8][2 * 64 * 32 * 64];
__device__ float g_kv[2 * 64 * 32 * 64];
__device__ float g_attn[64 * 32 * 32];
__device__ __half g_xsa[8u * 8u * 32u * 4096u];       // spatial out [b][h][d][n], fp16

// bf16 split operands for the tensor-core GEMM
__device__ __nv_bfloat16 g_Whi[1536 * 256];
__device__ __nv_bfloat16 g_Wlo[1536 * 256];
__device__ __nv_bfloat16 g_xhi[8u * 4096u * 256u];    // [b][n][c]  (transposed)
__device__ __nv_bfloat16 g_xlo[8u * 4096u * 256u];

// ---------------------------------------------------------------------------
// helpers
// ---------------------------------------------------------------------------
__device__ __forceinline__ uint32_t smem_u32(const void* p) {
    uint32_t a;
    asm("{ .reg .u64 t; cvta.to.shared.u64 t, %1; cvt.u32.u64 %0, t; }" : "=r"(a) : "l"(p));
    return a;
}
#define CP_ASYNC16(dst, src) \
    asm volatile("cp.async.cg.shared.global [%0], [%1], 16;" :: "r"(dst), "l"(src))
#define CP_COMMIT() asm volatile("cp.async.commit_group;" ::: "memory")
#define CP_WAIT1()  asm volatile("cp.async.wait_group 1;" ::: "memory")

__device__ __forceinline__ void mma_bf16(float* d, const uint32_t* a, const uint32_t* bb) {
    asm volatile(
        "mma.sync.aligned.m16n8k16.row.col.f32.bf16.bf16.f32 "
        "{%0,%1,%2,%3}, {%4,%5,%6,%7}, {%8,%9}, {%0,%1,%2,%3};"
        : "+f"(d[0]), "+f"(d[1]), "+f"(d[2]), "+f"(d[3])
        : "r"(a[0]), "r"(a[1]), "r"(a[2]), "r"(a[3]), "r"(bb[0]), "r"(bb[1]));
}

// FFMA-only exp: exp(x) = 2^(x*log2e), rint via magic number, 5-term poly for 2^f.
// Accurate to ~2e-6 relative on the softmax range; avoids the MUFU pipe entirely.
__device__ __forceinline__ float fexp(float x) {
    const float L2E = 1.4426950408889634f;
    float t = fmaf(x, L2E, 12582912.0f);       // 1.5*2^23 magic: rounds to nearest int
    float n = t - 12582912.0f;
    float f = fmaf(x, L2E, -n);                // f in [-0.5, 0.5]
    float p = 1.33978035e-3f;                  // exp(f*ln2) Taylor/minimax
    p = fmaf(p, f, 9.67770915e-3f);
    p = fmaf(p, f, 5.55041086e-2f);
    p = fmaf(p, f, 2.40226507e-1f);
    p = fmaf(p, f, 6.93147182e-1f);
    p = fmaf(p, f, 1.0f);
    int e = __float2int_rn(n);
    if (e < -126) e = -126;                    // flush deep underflow to ~0
    if (e > 126) e = 126;
    return __int_as_float((e + 127) << 23) * p;
}

// ---------------------------------------------------------------------------
// K0w: pack weights into bf16 hi/lo (GEMM row order) + zero g_sumsq.
// ---------------------------------------------------------------------------
__global__ __launch_bounds__(256) void k0w_pack(const float* __restrict__ Wsa,
                                                const float* __restrict__ Wsc) {
    int e = blockIdx.x * 256 + threadIdx.x;       // 0 .. 393215
    if (e < 3 * 2048) g_sumsq[e] = 0.f;
    int r = e >> 8, c = e & 255;
    int p = (r >= 768) ? 1 : 0;
    int rr = r - p * 768;
    int t = rr >> 8;
    const float* Wp = p ? Wsc : Wsa;
    int srow = rr + ((p == 0 && t == 2) ? 256 : 0);
    float v = Wp[(size_t)srow * 256 + c];
    __nv_bfloat16 hi = __float2bfloat16(v);
    float lo = v - __bfloat162float(hi);
    g_Whi[e] = hi;
    g_Wlo[e] = __float2bfloat16(lo);
}

// ---------------------------------------------------------------------------
// K0x: transpose x [b][c][n] -> [b][n][c] with bf16 hi/lo split.
// ---------------------------------------------------------------------------
__global__ __launch_bounds__(128) void k0x_pack(const float* __restrict__ x) {
    int n0 = blockIdx.x * 128;
    int b = blockIdx.y;
    __shared__ float sm[64][132];
    int tid = threadIdx.x;
    const float* xb = x + (size_t)b * C_ * N_;

    for (int c0 = 0; c0 < 256; c0 += 64) {
#pragma unroll
        for (int i = 0; i < 16; i++) {
            int u = tid + i * 128;
            int c = u >> 5, nq = u & 31;
            *(float4*)&sm[c][nq * 4] =
                *(const float4*)(xb + (size_t)(c0 + c) * N_ + n0 + nq * 4);
        }
        __syncthreads();
        uint32_t hibuf[32], lobuf[32];
#pragma unroll
        for (int c = 0; c < 64; c += 2) {
            float v0 = sm[c][tid], v1 = sm[c + 1][tid];
            __nv_bfloat16 h0 = __float2bfloat16(v0), h1 = __float2bfloat16(v1);
            __nv_bfloat16 l0 = __float2bfloat16(v0 - __bfloat162float(h0));
            __nv_bfloat16 l1 = __float2bfloat16(v1 - __bfloat162float(h1));
            hibuf[c >> 1] = (uint32_t)__bfloat16_as_ushort(h0) |
                            ((uint32_t)__bfloat16_as_ushort(h1) << 16);
            lobuf[c >> 1] = (uint32_t)__bfloat16_as_ushort(l0) |
                            ((uint32_t)__bfloat16_as_ushort(l1) << 16);
        }
        size_t obase = ((size_t)b * 4096 + n0 + tid) * 256 + c0;
#pragma unroll
        for (int j = 0; j < 8; j++) {
            *(uint4*)&g_xhi[obase + j * 8] = *(uint4*)&hibuf[j * 4];
            *(uint4*)&g_xlo[obase + j * 8] = *(uint4*)&lobuf[j * 4];
        }
        __syncthreads();
    }
}

// ---------------------------------------------------------------------------
// K1: mma.sync bf16-split GEMM, shared-tile formulation.
// Per k32 chunk: load the 4 distinct tiles {Whi, Wlo, xhi, xlo} ONCE,
// then accumulate all 3 split terms (hi*hi + hi*lo + lo*hi) into one D.
// CTA 128m x 128n; 8 warps (2m x 4n); 8 double-buffered steps.
// Dynamic smem: 2 bufs x 4 tiles x 128 x 40 halves = 81920 B.
// ---------------------------------------------------------------------------
#define K1_TSTRIDE 40
#define K1_TILE_HALVES (128 * K1_TSTRIDE)

__global__ __launch_bounds__(256) void k1_mma() {
    extern __shared__ __half sm1[];
    const int n0 = blockIdx.x * 128;
    const int my = blockIdx.y;                  // 0..11
    const int b  = blockIdx.z;
    const int m0 = my * 128;

    const int tid = threadIdx.x;
    const int wid = tid >> 5, lane = tid & 31;
    const int wm = (wid & 1) * 64, wn = (wid >> 1) * 32;
    const int g = lane >> 2, t4 = lane & 3;

#define TILE(buf, t) (sm1 + ((buf) * 4 + (t)) * K1_TILE_HALVES)

    float acc[4][4][4];
#pragma unroll
    for (int mt = 0; mt < 4; mt++)
#pragma unroll
        for (int nt = 0; nt < 4; nt++)
#pragma unroll
            for (int j = 0; j < 4; j++) acc[mt][nt][j] = 0.f;

    const int lr0 = tid >> 2;                   // rows 0..63
    const int ls0 = (tid & 3) * 8;              // half-offset of 16B seg

#define LOAD_STEP(kc, buf)                                                              \
    do {                                                                                \
        int _k0 = (kc) * 32;                                                            \
        const __nv_bfloat16* _Ah = g_Whi + (size_t)m0 * 256 + _k0;                      \
        const __nv_bfloat16* _Al = g_Wlo + (size_t)m0 * 256 + _k0;                      \
        const __nv_bfloat16* _Bh = g_xhi + ((size_t)b * 4096 + n0) * 256 + _k0;         \
        const __nv_bfloat16* _Bl = g_xlo + ((size_t)b * 4096 + n0) * 256 + _k0;         \
        CP_ASYNC16(smem_u32(TILE(buf,0) + lr0 * K1_TSTRIDE + ls0), _Ah + (size_t)lr0 * 256 + ls0); \
        CP_ASYNC16(smem_u32(TILE(buf,0) + (lr0+64) * K1_TSTRIDE + ls0), _Ah + (size_t)(lr0+64) * 256 + ls0); \
        CP_ASYNC16(smem_u32(TILE(buf,1) + lr0 * K1_TSTRIDE + ls0), _Al + (size_t)lr0 * 256 + ls0); \
        CP_ASYNC16(smem_u32(TILE(buf,1) + (lr0+64) * K1_TSTRIDE + ls0), _Al + (size_t)(lr0+64) * 256 + ls0); \
        CP_ASYNC16(smem_u32(TILE(buf,2) + lr0 * K1_TSTRIDE + ls0), _Bh + (size_t)lr0 * 256 + ls0); \
        CP_ASYNC16(smem_u32(TILE(buf,2) + (lr0+64) * K1_TSTRIDE + ls0), _Bh + (size_t)(lr0+64) * 256 + ls0); \
        CP_ASYNC16(smem_u32(TILE(buf,3) + lr0 * K1_TSTRIDE + ls0), _Bl + (size_t)lr0 * 256 + ls0); \
        CP_ASYNC16(smem_u32(TILE(buf,3) + (lr0+64) * K1_TSTRIDE + ls0), _Bl + (size_t)(lr0+64) * 256 + ls0); \
    } while (0)

    LOAD_STEP(0, 0); CP_COMMIT();
    LOAD_STEP(1, 1); CP_COMMIT();

    for (int s = 0; s < 8; s++) {
        const int buf = s & 1;
        CP_WAIT1();
        __syncthreads();

#pragma unroll
        for (int h = 0; h < 2; h++) {
            uint32_t af[4][4], bh2[4][2], bl2[4][2];
            // B fragments (hi and lo)
#pragma unroll
            for (int nt = 0; nt < 4; nt++) {
                const __half* nbh = TILE(buf,2) + (wn + nt * 8 + g) * K1_TSTRIDE + h * 16;
                const __half* nbl = TILE(buf,3) + (wn + nt * 8 + g) * K1_TSTRIDE + h * 16;
                bh2[nt][0] = *(const uint32_t*)(nbh + 2 * t4);
                bh2[nt][1] = *(const uint32_t*)(nbh + 2 * t4 + 8);
                bl2[nt][0] = *(const uint32_t*)(nbl + 2 * t4);
                bl2[nt][1] = *(const uint32_t*)(nbl + 2 * t4 + 8);
            }
            // A-hi fragments; terms 1 & 2
#pragma unroll
            for (int mt = 0; mt < 4; mt++) {
                const __half* base = TILE(buf,0) + (wm + mt * 16 + g) * K1_TSTRIDE + h * 16;
                af[mt][0] = *(const uint32_t*)(base + 2 * t4);
                af[mt][1] = *(const uint32_t*)(base + 8 * K1_TSTRIDE + 2 * t4);
                af[mt][2] = *(const uint32_t*)(base + 2 * t4 + 8);
                af[mt][3] = *(const uint32_t*)(base + 8 * K1_TSTRIDE + 2 * t4 + 8);
            }
#pragma unroll
            for (int mt = 0; mt < 4; mt++)
#pragma unroll
                for (int nt = 0; nt < 4; nt++) {
                    mma_bf16(acc[mt][nt], af[mt], bh2[nt]);
                    mma_bf16(acc[mt][nt], af[mt], bl2[nt]);
                }
            // A-lo fragments; term 3
#pragma unroll
            for (int mt = 0; mt < 4; mt++) {
                const __half* base = TILE(buf,1) + (wm + mt * 16 + g) * K1_TSTRIDE + h * 16;
                af[mt][0] = *(const uint32_t*)(base + 2 * t4);
                af[mt][1] = *(const uint32_t*)(base + 8 * K1_TSTRIDE + 2 * t4);
                af[mt][2] = *(const uint32_t*)(base + 2 * t4 + 8);
                af[mt][3] = *(const uint32_t*)(base + 8 * K1_TSTRIDE + 2 * t4 + 8);
            }
#pragma unroll
            for (int mt = 0; mt < 4; mt++)
#pragma unroll
                for (int nt = 0; nt < 4; nt++)
                    mma_bf16(acc[mt][nt], af[mt], bh2[nt]);
        }

        __syncthreads();
        if (s + 2 < 8) LOAD_STEP(s + 2, buf);
        CP_COMMIT();
    }
#undef LOAD_STEP
#undef TILE

    // epilogue -> g_proj (fp16) + fused sumsq for slabs 0,3,4
    const int slab = my >> 1;
    const int rb = (my & 1) * 128;
    const int which = (slab == 0) ? 0 : (slab == 3 ? 1 : (slab == 4 ? 2 : -1));
#pragma unroll
    for (int mt = 0; mt < 4; mt++) {
        int r0 = rb + wm + mt * 16 + g;
        __half* p0 = g_proj + (((size_t)slab * 8 + b) * 256 + r0) * (size_t)N_ + n0 + wn;
        __half* p1 = p0 + 8 * (size_t)N_;
        float ss0 = 0.f, ss1 = 0.f;
#pragma unroll
        for (int nt = 0; nt < 4; nt++) {
            float a0 = acc[mt][nt][0], a1 = acc[mt][nt][1];
            float a2 = acc[mt][nt][2], a3 = acc[mt][nt][3];
            *(__half2*)(p0 + nt * 8 + 2 * t4) = __floats2half2_rn(a0, a1);
            *(__half2*)(p1 + nt * 8 + 2 * t4) = __floats2half2_rn(a2, a3);
            ss0 += a0 * a0 + a1 * a1;
            ss1 += a2 * a2 + a3 * a3;
        }
        if (which >= 0) {
            ss0 += __shfl_xor_sync(0xffffffffu, ss0, 1);
            ss0 += __shfl_xor_sync(0xffffffffu, ss0, 2);
            ss1 += __shfl_xor_sync(0xffffffffu, ss1, 1);
            ss1 += __shfl_xor_sync(0xffffffffu, ss1, 2);
            if (t4 == 0) {
                int row = b * 256 + r0;
                atomicAdd(&g_sumsq[which * 2048 + row], ss0);
                atomicAdd(&g_sumsq[which * 2048 + row + 8], ss1);
            }
        }
    }
}

// ---------------------------------------------------------------------------
// K1n: finalize inverse norms
// ---------------------------------------------------------------------------
__global__ __launch_bounds__(256) void k1n_inv() {
    int i = blockIdx.x * 256 + threadIdx.x;      // 6144
    g_inv[i] = 1.f / fmaxf(sqrtf(g_sumsq[i]), 1e-12f);
}

// ---------------------------------------------------------------------------
// K3: Linformer projection: g_kv[s][bh][d][p] = sum_n T[s][bh][d][n] * EF[n][p]
// ---------------------------------------------------------------------------
__global__ __launch_bounds__(256) void k3_kvproj(const float* __restrict__ EF) {
    int s  = blockIdx.x >> 6;
    int bh = blockIdx.x & 63;
    int sp = blockIdx.y;
    const __half* src = g_proj + ((size_t)(1 + s) * 2048 + bh * 32) * N_;
    __shared__ float EFs[64][64];
    __shared__ float Xs[32][65];
    int tid = threadIdx.x;
    int dd = tid & 31, pg = tid >> 5;
    float acc[8];
#pragma unroll
    for (int j = 0; j < 8; j++) acc[j] = 0.f;

    for (int c = 0; c < 8; c++) {
        int nb = sp * 512 + c * 64;
#pragma unroll
        for (int i = 0; i < 4; i++) {
            int f = tid + i * 256;
            int nn = f >> 4, pq = f & 15;
            *(float4*)&EFs[nn][pq * 4] = *(const float4*)(EF + (size_t)(nb + nn) * 64 + pq * 4);
        }
#pragma unroll
        for (int i = 0; i < 8; i++) {
            int f = tid + i * 256;
            int r = f >> 6, j = f & 63;
            Xs[r][j] = __half2float(src[(size_t)r * N_ + nb + j]);
        }
        __syncthreads();
#pragma unroll 4
        for (int nn = 0; nn < 64; nn++) {
            float xv = Xs[dd][nn];
            float4 e0 = *(const float4*)&EFs[nn][pg * 8];
            float4 e1 = *(const float4*)&EFs[nn][pg * 8 + 4];
            acc[0] += xv * e0.x; acc[1] += xv * e0.y;
            acc[2] += xv * e0.z; acc[3] += xv * e0.w;
            acc[4] += xv * e1.x; acc[5] += xv * e1.y;
            acc[6] += xv * e1.z; acc[7] += xv * e1.w;
        }
        __syncthreads();
    }
    float* o = &g_kvp[sp][((s * 64 + bh) * 32 + dd) * 64 + pg * 8];
    *(float4*)&o[0] = make_float4(acc[0], acc[1], acc[2], acc[3]);
    *(float4*)&o[4] = make_float4(acc[4], acc[5], acc[6], acc[7]);
}

__global__ __launch_bounds__(256) void k3r_reduce() {
    int i = blockIdx.x * 256 + threadIdx.x;
    float s = 0.f;
#pragma unroll
    for (int sp = 0; sp < 8; sp++) s += g_kvp[sp][i];
    g_kv[i] = s;
}

// ---------------------------------------------------------------------------
// K4: spatial attention (FFMA-only exp)
// ---------------------------------------------------------------------------
__global__ __launch_bounds__(256) void k4_spatial(const float* __restrict__ temp2_sa) {
    int ch = blockIdx.x, bh = blockIdx.y;
    int h = bh & 7;
    __shared__ float Ks[32][64], Vs[32][64];
    int tid = threadIdx.x;
    float* ksf = &Ks[0][0];
    float* vsf = &Vs[0][0];
    for (int i = tid; i < 2048; i += 256) {
        ksf[i] = g_kv[(0 * 64 + bh) * 2048 + i];
        vsf[i] = g_kv[(1 * 64 + bh) * 2048 + i];
    }
    __syncthreads();

    int n = ch * 256 + tid;
    const __half* qb = g_proj + (size_t)(bh * 32) * N_ + n;
    const float* iv = g_inv + bh * 32;
    float temp = temp2_sa[h];

    float qn[32];
#pragma unroll
    for (int d = 0; d < 32; d++) qn[d] = __half2float(qb[(size_t)d * N_]) * iv[d];

    float s[64];
#pragma unroll
    for (int j = 0; j < 64; j++) s[j] = 0.f;
#pragma unroll
    for (int d = 0; d < 32; d++) {
        float q = qn[d];
#pragma unroll
        for (int pq = 0; pq < 16; pq++) {
            float4 k4 = *(const float4*)&Ks[d][pq * 4];
            s[pq * 4 + 0] += q * k4.x;
            s[pq * 4 + 1] += q * k4.y;
            s[pq * 4 + 2] += q * k4.z;
            s[pq * 4 + 3] += q * k4.w;
        }
    }
    float mx = -1e30f;
#pragma unroll
    for (int j = 0; j < 64; j++) { s[j] *= temp; mx = fmaxf(mx, s[j]); }
    float sum = 0.f;
#pragma unroll
    for (int j = 0; j < 64; j++) { float e = fexp(s[j] - mx); s[j] = e; sum += e; }
    float isum = 1.f / sum;

    __half* ob = g_xsa + (size_t)(bh * 32) * N_ + n;
#pragma unroll
    for (int d = 0; d < 32; d++) {
        float o = 0.f;
#pragma unroll
        for (int pq = 0; pq < 16; pq++) {
            float4 v4 = *(const float4*)&Vs[d][pq * 4];
            o += s[pq * 4 + 0] * v4.x + s[pq * 4 + 1] * v4.y +
                 s[pq * 4 + 2] * v4.z + s[pq * 4 + 3] * v4.w;
        }
        ob[(size_t)d * N_] = __float2half(o * isum);
    }
}

// ---------------------------------------------------------------------------
// K5: channel gram + softmax
// ---------------------------------------------------------------------------
__global__ __launch_bounds__(256) void k5_gram(const float* __restrict__ temp_sc) {
    int bh = blockIdx.x;
    int h = bh & 7;
    __shared__ float qcs[32][133], kcs[32][133];
    __shared__ float att[32][33];
    int tid = threadIdx.x;
    int ddp = tid >> 4, ep = tid & 15;
    float a00 = 0.f, a01 = 0.f, a10 = 0.f, a11 = 0.f;
    const __half* qsrc = g_proj + ((size_t)3 * 2048 + bh * 32) * N_;
    const __half* ksrc = g_proj + ((size_t)4 * 2048 + bh * 32) * N_;

    for (int c0 = 0; c0 < N_; c0 += 128) {
#pragma unroll
        for (int i = 0; i < 16; i++) {
            int f = tid + i * 256;
            int r = f >> 7, j = f & 127;
            qcs[r][j] = __half2float(qsrc[(size_t)r * N_ + c0 + j]);
            kcs[r][j] = __half2float(ksrc[(size_t)r * N_ + c0 + j]);
        }
        __syncthreads();
#pragma unroll 4
        for (int nn = 0; nn < 128; nn++) {
            float q0 = qcs[2 * ddp][nn], q1 = qcs[2 * ddp + 1][nn];
            float k0 = kcs[2 * ep][nn],  k1 = kcs[2 * ep + 1][nn];
            a00 += q0 * k0; a01 += q0 * k1;
            a10 += q1 * k0; a11 += q1 * k1;
        }
        __syncthreads();
    }
    const float* ivq = g_inv + 2048 + bh * 32;
    const float* ivk = g_inv + 4096 + bh * 32;
    float temp = temp_sc[h];
    att[2 * ddp][2 * ep]         = a00 * ivq[2 * ddp]     * ivk[2 * ep]     * temp;
    att[2 * ddp][2 * ep + 1]     = a01 * ivq[2 * ddp]     * ivk[2 * ep + 1] * temp;
    att[2 * ddp + 1][2 * ep]     = a10 * ivq[2 * ddp + 1] * ivk[2 * ep]     * temp;
    att[2 * ddp + 1][2 * ep + 1] = a11 * ivq[2 * ddp + 1] * ivk[2 * ep + 1] * temp;
    __syncthreads();

    int w = tid >> 5, l = tid & 31;
#pragma unroll
    for (int r0 = 0; r0 < 4; r0++) {
        int r = w * 4 + r0;
        float v = att[r][l];
        float m = v;
#pragma unroll
        for (int o = 16; o > 0; o >>= 1) m = fmaxf(m, __shfl_xor_sync(0xffffffffu, m, o));
        float e = fexp(v - m);
        float sum = e;
#pragma unroll
        for (int o = 16; o > 0; o >>= 1) sum += __shfl_xor_sync(0xffffffffu, sum, o);
        g_attn[bh * 1024 + r * 32 + l] = e / sum;
    }
}

// ---------------------------------------------------------------------------
// K6: combine
// ---------------------------------------------------------------------------
__global__ __launch_bounds__(128) void k6_combine(float* __restrict__ out) {
    int ch = blockIdx.x;
    int bh = blockIdx.y;
    int b = bh >> 3, h = bh & 7;
    __shared__ float vcs[32][128];
    __shared__ float sas[128][33];
    __shared__ float att[1024];
    int tid = threadIdx.x;

    const __half* vsrc = g_proj + ((size_t)5 * 2048 + bh * 32) * N_ + ch * 128;
#pragma unroll
    for (int i = 0; i < 32; i++) {
        int f = tid + i * 128;
        int e = f >> 7, j = f & 127;
        vcs[e][j] = __half2float(vsrc[(size_t)e * N_ + j]);
    }
#pragma unroll
    for (int i = 0; i < 32; i++) {
        int f = tid + i * 128;
        int tp = f >> 5, dc = f & 31;
        sas[tp][dc] = __half2float(g_xsa[((size_t)(b * 8 + (tp >> 4)) * 32 + ch) * N_ +
                                         (tp & 15) * 256 + h * 32 + dc]);
    }
#pragma unroll
    for (int i = 0; i < 8; i++) att[tid + i * 128] = g_attn[bh * 1024 + tid + i * 128];
    __syncthreads();

    float acc[32];
#pragma unroll
    for (int dc = 0; dc < 32; dc++) acc[dc] = 0.f;
#pragma unroll 4
    for (int e = 0; e < 32; e++) {
        float v = vcs[e][tid];
#pragma unroll
        for (int dc = 0; dc < 32; dc++) acc[dc] += att[dc * 32 + e] * v;
    }
    float* ob = out + (size_t)(b * 256 + h * 32) * N_ + ch * 128 + tid;
#pragma unroll
    for (int dc = 0; dc < 32; dc++) ob[(size_t)dc * N_] = acc[dc] + sas[tid][dc];
}

// ---------------------------------------------------------------------------
extern "C" void kernel_launch(void* const* d_in, const int* in_sizes, int n_in,
                              void* d_out, int out_size) {
    const float* x    = (const float*)d_in[0];
    const float* Wsa  = (const float*)d_in[1];
    const float* EF   = (const float*)d_in[2];
    const float* t2sa = (const float*)d_in[3];
    const float* Wsc  = (const float*)d_in[4];
    const float* tsc  = (const float*)d_in[5];
    float* out = (float*)d_out;

    const int k1_smem = 2 * 4 * K1_TILE_HALVES * (int)sizeof(__half);  // 81920
    cudaFuncSetAttribute(k1_mma, cudaFuncAttributeMaxDynamicSharedMemorySize, k1_smem);

    k0w_pack<<<1536, 256>>>(Wsa, Wsc);
    k0x_pack<<<dim3(32, 8), 128>>>(x);
    k1_mma<<<dim3(32, 12, 8), 256, k1_smem>>>();
    k1n_inv<<<24, 256>>>();
    k3_kvproj<<<dim3(128, 8), 256>>>(EF);
    k3r_reduce<<<1024, 256>>>();
    k4_spatial<<<dim3(16, 64), 256>>>(t2sa);
    k5_gram<<<64, 256>>>(tsc);
    k6_combine<<<dim3(32, 64), 128>>>(out);
}

// round 9
// speedup vs baseline: 1.9207x; 1.2692x over previous
#include <cuda_runtime.h>
#include <cuda_bf16.h>
#include <cuda_fp16.h>
#include <math.h>
#include <stdint.h>

// Problem constants
#define B_ 8
#define C_ 256
#define N_ 4096
#define H_ 8
#define D_ 32
#define P_ 64

// Scratch (device globals; allocation-free contract)
// g_proj layout: [slab][b][row256][n] (fp16), slab: 0=q_sa,1=k_sa,2=v_sa,3=q_c,4=k_c,5=v_c
__device__ __half g_proj[6u * 8u * 256u * 4096u];     // 100 MB
__device__ float g_sumsq[3 * 2048];                   // row sum-of-squares (atomic)
__device__ float g_kvp[8][2 * 64 * 32 * 64];
__device__ float g_kv[2 * 64 * 32 * 64];
__device__ float g_attn[64 * 32 * 32];
__device__ __half g_xsa[8u * 8u * 32u * 4096u];       // spatial out [b][h][d][n], fp16

// fp16 operands for the tensor-core GEMM
__device__ __half g_Wh[1536 * 256];
__device__ __half g_xh[8u * 4096u * 256u];            // [b][n][c]  (transposed)

// ---------------------------------------------------------------------------
// helpers
// ---------------------------------------------------------------------------
__device__ __forceinline__ uint32_t smem_u32(const void* p) {
    uint32_t a;
    asm("{ .reg .u64 t; cvta.to.shared.u64 t, %1; cvt.u32.u64 %0, t; }" : "=r"(a) : "l"(p));
    return a;
}
#define CP_ASYNC16(dst, src) \
    asm volatile("cp.async.cg.shared.global [%0], [%1], 16;" :: "r"(dst), "l"(src))
#define CP_COMMIT() asm volatile("cp.async.commit_group;" ::: "memory")
#define CP_WAIT1()  asm volatile("cp.async.wait_group 1;" ::: "memory")

__device__ __forceinline__ void mma_f16(float* d, const uint32_t* a, const uint32_t* bb) {
    asm volatile(
        "mma.sync.aligned.m16n8k16.row.col.f32.f16.f16.f32 "
        "{%0,%1,%2,%3}, {%4,%5,%6,%7}, {%8,%9}, {%0,%1,%2,%3};"
        : "+f"(d[0]), "+f"(d[1]), "+f"(d[2]), "+f"(d[3])
        : "r"(a[0]), "r"(a[1]), "r"(a[2]), "r"(a[3]), "r"(bb[0]), "r"(bb[1]));
}

// FFMA-only exp (avoids MUFU pipe), ~2e-6 relative accuracy.
__device__ __forceinline__ float fexp(float x) {
    const float L2E = 1.4426950408889634f;
    float t = fmaf(x, L2E, 12582912.0f);
    float n = t - 12582912.0f;
    float f = fmaf(x, L2E, -n);
    float p = 1.33978035e-3f;
    p = fmaf(p, f, 9.67770915e-3f);
    p = fmaf(p, f, 5.55041086e-2f);
    p = fmaf(p, f, 2.40226507e-1f);
    p = fmaf(p, f, 6.93147182e-1f);
    p = fmaf(p, f, 1.0f);
    int e = __float2int_rn(n);
    if (e < -126) e = -126;
    if (e > 126) e = 126;
    return __int_as_float((e + 127) << 23) * p;
}

__device__ __forceinline__ float inv_norm(float ss) {
    return 1.f / fmaxf(sqrtf(ss), 1e-12f);
}

// ---------------------------------------------------------------------------
// K0w: pack weights into fp16 (GEMM row order) + zero g_sumsq.
// ---------------------------------------------------------------------------
__global__ __launch_bounds__(256) void k0w_pack(const float* __restrict__ Wsa,
                                                const float* __restrict__ Wsc) {
    int e = blockIdx.x * 256 + threadIdx.x;       // 0 .. 393215
    if (e < 3 * 2048) g_sumsq[e] = 0.f;
    int r = e >> 8, c = e & 255;
    int p = (r >= 768) ? 1 : 0;
    int rr = r - p * 768;
    int t = rr >> 8;
    const float* Wp = p ? Wsc : Wsa;
    int srow = rr + ((p == 0 && t == 2) ? 256 : 0);
    g_Wh[e] = __float2half(Wp[(size_t)srow * 256 + c]);
}

// ---------------------------------------------------------------------------
// K0x: transpose x [b][c][n] -> [b][n][c], fp16.
// ---------------------------------------------------------------------------
__global__ __launch_bounds__(128) void k0x_pack(const float* __restrict__ x) {
    int n0 = blockIdx.x * 128;
    int b = blockIdx.y;
    __shared__ float sm[64][132];
    int tid = threadIdx.x;
    const float* xb = x + (size_t)b * C_ * N_;

    for (int c0 = 0; c0 < 256; c0 += 64) {
#pragma unroll
        for (int i = 0; i < 16; i++) {
            int u = tid + i * 128;
            int c = u >> 5, nq = u & 31;
            *(float4*)&sm[c][nq * 4] =
                *(const float4*)(xb + (size_t)(c0 + c) * N_ + n0 + nq * 4);
        }
        __syncthreads();
        uint32_t buf[32];
#pragma unroll
        for (int c = 0; c < 64; c += 2) {
            __half2 hv = __floats2half2_rn(sm[c][tid], sm[c + 1][tid]);
            buf[c >> 1] = *(uint32_t*)&hv;
        }
        size_t obase = ((size_t)b * 4096 + n0 + tid) * 256 + c0;
#pragma unroll
        for (int j = 0; j < 8; j++)
            *(uint4*)&g_xh[obase + j * 8] = *(uint4*)&buf[j * 4];
        __syncthreads();
    }
}

// ---------------------------------------------------------------------------
// K1: fp16 mma.sync GEMM.  D[m][n] = sum_c W[m][c] * x[b][c][n]
// CTA 128m x 128n; 8 warps (2m x 4n); 8 double-buffered k32 steps.
// smem: 2 bufs x 2 tiles x 128 x 40 halves = 40960 B.
// ---------------------------------------------------------------------------
#define K1_TSTRIDE 40
#define K1_TILE_HALVES (128 * K1_TSTRIDE)

__global__ __launch_bounds__(256) void k1_mma() {
    extern __shared__ __half sm1[];
    const int n0 = blockIdx.x * 128;
    const int my = blockIdx.y;                  // 0..11
    const int b  = blockIdx.z;
    const int m0 = my * 128;

    const int tid = threadIdx.x;
    const int wid = tid >> 5, lane = tid & 31;
    const int wm = (wid & 1) * 64, wn = (wid >> 1) * 32;
    const int g = lane >> 2, t4 = lane & 3;

#define TILE(buf, t) (sm1 + ((buf) * 2 + (t)) * K1_TILE_HALVES)

    float acc[4][4][4];
#pragma unroll
    for (int mt = 0; mt < 4; mt++)
#pragma unroll
        for (int nt = 0; nt < 4; nt++)
#pragma unroll
            for (int j = 0; j < 4; j++) acc[mt][nt][j] = 0.f;

    const int lr0 = tid >> 2;                   // rows 0..63
    const int ls0 = (tid & 3) * 8;              // half-offset of 16B seg

#define LOAD_STEP(kc, buf)                                                              \
    do {                                                                                \
        int _k0 = (kc) * 32;                                                            \
        const __half* _A = g_Wh + (size_t)m0 * 256 + _k0;                               \
        const __half* _B = g_xh + ((size_t)b * 4096 + n0) * 256 + _k0;                  \
        CP_ASYNC16(smem_u32(TILE(buf,0) + lr0 * K1_TSTRIDE + ls0), _A + (size_t)lr0 * 256 + ls0); \
        CP_ASYNC16(smem_u32(TILE(buf,0) + (lr0+64) * K1_TSTRIDE + ls0), _A + (size_t)(lr0+64) * 256 + ls0); \
        CP_ASYNC16(smem_u32(TILE(buf,1) + lr0 * K1_TSTRIDE + ls0), _B + (size_t)lr0 * 256 + ls0); \
        CP_ASYNC16(smem_u32(TILE(buf,1) + (lr0+64) * K1_TSTRIDE + ls0), _B + (size_t)(lr0+64) * 256 + ls0); \
    } while (0)

    LOAD_STEP(0, 0); CP_COMMIT();
    LOAD_STEP(1, 1); CP_COMMIT();

    for (int s = 0; s < 8; s++) {
        const int buf = s & 1;
        CP_WAIT1();
        __syncthreads();

#pragma unroll
        for (int h = 0; h < 2; h++) {
            uint32_t af[4][4], bfr[4][2];
#pragma unroll
            for (int mt = 0; mt < 4; mt++) {
                const __half* base = TILE(buf,0) + (wm + mt * 16 + g) * K1_TSTRIDE + h * 16;
                af[mt][0] = *(const uint32_t*)(base + 2 * t4);
                af[mt][1] = *(const uint32_t*)(base + 8 * K1_TSTRIDE + 2 * t4);
                af[mt][2] = *(const uint32_t*)(base + 2 * t4 + 8);
                af[mt][3] = *(const uint32_t*)(base + 8 * K1_TSTRIDE + 2 * t4 + 8);
            }
#pragma unroll
            for (int nt = 0; nt < 4; nt++) {
                const __half* nb = TILE(buf,1) + (wn + nt * 8 + g) * K1_TSTRIDE + h * 16;
                bfr[nt][0] = *(const uint32_t*)(nb + 2 * t4);
                bfr[nt][1] = *(const uint32_t*)(nb + 2 * t4 + 8);
            }
#pragma unroll
            for (int mt = 0; mt < 4; mt++)
#pragma unroll
                for (int nt = 0; nt < 4; nt++)
                    mma_f16(acc[mt][nt], af[mt], bfr[nt]);
        }

        __syncthreads();
        if (s + 2 < 8) LOAD_STEP(s + 2, buf);
        CP_COMMIT();
    }
#undef LOAD_STEP
#undef TILE

    // epilogue -> g_proj (fp16) + fused sumsq for slabs 0,3,4
    const int slab = my >> 1;
    const int rb = (my & 1) * 128;
    const int which = (slab == 0) ? 0 : (slab == 3 ? 1 : (slab == 4 ? 2 : -1));
#pragma unroll
    for (int mt = 0; mt < 4; mt++) {
        int r0 = rb + wm + mt * 16 + g;
        __half* p0 = g_proj + (((size_t)slab * 8 + b) * 256 + r0) * (size_t)N_ + n0 + wn;
        __half* p1 = p0 + 8 * (size_t)N_;
        float ss0 = 0.f, ss1 = 0.f;
#pragma unroll
        for (int nt = 0; nt < 4; nt++) {
            float a0 = acc[mt][nt][0], a1 = acc[mt][nt][1];
            float a2 = acc[mt][nt][2], a3 = acc[mt][nt][3];
            *(__half2*)(p0 + nt * 8 + 2 * t4) = __floats2half2_rn(a0, a1);
            *(__half2*)(p1 + nt * 8 + 2 * t4) = __floats2half2_rn(a2, a3);
            ss0 += a0 * a0 + a1 * a1;
            ss1 += a2 * a2 + a3 * a3;
        }
        if (which >= 0) {
            ss0 += __shfl_xor_sync(0xffffffffu, ss0, 1);
            ss0 += __shfl_xor_sync(0xffffffffu, ss0, 2);
            ss1 += __shfl_xor_sync(0xffffffffu, ss1, 1);
            ss1 += __shfl_xor_sync(0xffffffffu, ss1, 2);
            if (t4 == 0) {
                int row = b * 256 + r0;
                atomicAdd(&g_sumsq[which * 2048 + row], ss0);
                atomicAdd(&g_sumsq[which * 2048 + row + 8], ss1);
            }
        }
    }
}

// ---------------------------------------------------------------------------
// K3: Linformer projection: g_kv[s][bh][d][p] = sum_n T[s][bh][d][n] * EF[n][p]
// ---------------------------------------------------------------------------
__global__ __launch_bounds__(256) void k3_kvproj(const float* __restrict__ EF) {
    int s  = blockIdx.x >> 6;
    int bh = blockIdx.x & 63;
    int sp = blockIdx.y;
    const __half* src = g_proj + ((size_t)(1 + s) * 2048 + bh * 32) * N_;
    __shared__ float EFs[64][64];
    __shared__ float Xs[32][65];
    int tid = threadIdx.x;
    int dd = tid & 31, pg = tid >> 5;
    float acc[8];
#pragma unroll
    for (int j = 0; j < 8; j++) acc[j] = 0.f;

    for (int c = 0; c < 8; c++) {
        int nb = sp * 512 + c * 64;
#pragma unroll
        for (int i = 0; i < 4; i++) {
            int f = tid + i * 256;
            int nn = f >> 4, pq = f & 15;
            *(float4*)&EFs[nn][pq * 4] = *(const float4*)(EF + (size_t)(nb + nn) * 64 + pq * 4);
        }
#pragma unroll
        for (int i = 0; i < 8; i++) {
            int f = tid + i * 256;
            int r = f >> 6, j = f & 63;
            Xs[r][j] = __half2float(src[(size_t)r * N_ + nb + j]);
        }
        __syncthreads();
#pragma unroll 4
        for (int nn = 0; nn < 64; nn++) {
            float xv = Xs[dd][nn];
            float4 e0 = *(const float4*)&EFs[nn][pg * 8];
            float4 e1 = *(const float4*)&EFs[nn][pg * 8 + 4];
            acc[0] += xv * e0.x; acc[1] += xv * e0.y;
            acc[2] += xv * e0.z; acc[3] += xv * e0.w;
            acc[4] += xv * e1.x; acc[5] += xv * e1.y;
            acc[6] += xv * e1.z; acc[7] += xv * e1.w;
        }
        __syncthreads();
    }
    float* o = &g_kvp[sp][((s * 64 + bh) * 32 + dd) * 64 + pg * 8];
    *(float4*)&o[0] = make_float4(acc[0], acc[1], acc[2], acc[3]);
    *(float4*)&o[4] = make_float4(acc[4], acc[5], acc[6], acc[7]);
}

__global__ __launch_bounds__(256) void k3r_reduce() {
    int i = blockIdx.x * 256 + threadIdx.x;
    float s = 0.f;
#pragma unroll
    for (int sp = 0; sp < 8; sp++) s += g_kvp[sp][i];
    g_kv[i] = s;
}

// ---------------------------------------------------------------------------
// K4: spatial attention (inline inverse norms)
// ---------------------------------------------------------------------------
__global__ __launch_bounds__(256) void k4_spatial(const float* __restrict__ temp2_sa) {
    int ch = blockIdx.x, bh = blockIdx.y;
    int h = bh & 7;
    __shared__ float Ks[32][64], Vs[32][64];
    __shared__ float ivs[32];
    int tid = threadIdx.x;
    float* ksf = &Ks[0][0];
    float* vsf = &Vs[0][0];
    for (int i = tid; i < 2048; i += 256) {
        ksf[i] = g_kv[(0 * 64 + bh) * 2048 + i];
        vsf[i] = g_kv[(1 * 64 + bh) * 2048 + i];
    }
    if (tid < 32) ivs[tid] = inv_norm(g_sumsq[bh * 32 + tid]);
    __syncthreads();

    int n = ch * 256 + tid;
    const __half* qb = g_proj + (size_t)(bh * 32) * N_ + n;
    float temp = temp2_sa[h];

    float qn[32];
#pragma unroll
    for (int d = 0; d < 32; d++) qn[d] = __half2float(qb[(size_t)d * N_]) * ivs[d];

    float s[64];
#pragma unroll
    for (int j = 0; j < 64; j++) s[j] = 0.f;
#pragma unroll
    for (int d = 0; d < 32; d++) {
        float q = qn[d];
#pragma unroll
        for (int pq = 0; pq < 16; pq++) {
            float4 k4 = *(const float4*)&Ks[d][pq * 4];
            s[pq * 4 + 0] += q * k4.x;
            s[pq * 4 + 1] += q * k4.y;
            s[pq * 4 + 2] += q * k4.z;
            s[pq * 4 + 3] += q * k4.w;
        }
    }
    float mx = -1e30f;
#pragma unroll
    for (int j = 0; j < 64; j++) { s[j] *= temp; mx = fmaxf(mx, s[j]); }
    float sum = 0.f;
#pragma unroll
    for (int j = 0; j < 64; j++) { float e = fexp(s[j] - mx); s[j] = e; sum += e; }
    float isum = 1.f / sum;

    __half* ob = g_xsa + (size_t)(bh * 32) * N_ + n;
#pragma unroll
    for (int d = 0; d < 32; d++) {
        float o = 0.f;
#pragma unroll
        for (int pq = 0; pq < 16; pq++) {
            float4 v4 = *(const float4*)&Vs[d][pq * 4];
            o += s[pq * 4 + 0] * v4.x + s[pq * 4 + 1] * v4.y +
                 s[pq * 4 + 2] * v4.z + s[pq * 4 + 3] * v4.w;
        }
        ob[(size_t)d * N_] = __float2half(o * isum);
    }
}

// ---------------------------------------------------------------------------
// K5: channel gram + softmax (inline inverse norms)
// ---------------------------------------------------------------------------
__global__ __launch_bounds__(256) void k5_gram(const float* __restrict__ temp_sc) {
    int bh = blockIdx.x;
    int h = bh & 7;
    __shared__ float qcs[32][133], kcs[32][133];
    __shared__ float att[32][33];
    int tid = threadIdx.x;
    int ddp = tid >> 4, ep = tid & 15;
    float a00 = 0.f, a01 = 0.f, a10 = 0.f, a11 = 0.f;
    const __half* qsrc = g_proj + ((size_t)3 * 2048 + bh * 32) * N_;
    const __half* ksrc = g_proj + ((size_t)4 * 2048 + bh * 32) * N_;

    for (int c0 = 0; c0 < N_; c0 += 128) {
#pragma unroll
        for (int i = 0; i < 16; i++) {
            int f = tid + i * 256;
            int r = f >> 7, j = f & 127;
            qcs[r][j] = __half2float(qsrc[(size_t)r * N_ + c0 + j]);
            kcs[r][j] = __half2float(ksrc[(size_t)r * N_ + c0 + j]);
        }
        __syncthreads();
#pragma unroll 4
        for (int nn = 0; nn < 128; nn++) {
            float q0 = qcs[2 * ddp][nn], q1 = qcs[2 * ddp + 1][nn];
            float k0 = kcs[2 * ep][nn],  k1 = kcs[2 * ep + 1][nn];
            a00 += q0 * k0; a01 += q0 * k1;
            a10 += q1 * k0; a11 += q1 * k1;
        }
        __syncthreads();
    }
    float temp = temp_sc[h];
    float ivq0 = inv_norm(g_sumsq[2048 + bh * 32 + 2 * ddp]);
    float ivq1 = inv_norm(g_sumsq[2048 + bh * 32 + 2 * ddp + 1]);
    float ivk0 = inv_norm(g_sumsq[4096 + bh * 32 + 2 * ep]);
    float ivk1 = inv_norm(g_sumsq[4096 + bh * 32 + 2 * ep + 1]);
    att[2 * ddp][2 * ep]         = a00 * ivq0 * ivk0 * temp;
    att[2 * ddp][2 * ep + 1]     = a01 * ivq0 * ivk1 * temp;
    att[2 * ddp + 1][2 * ep]     = a10 * ivq1 * ivk0 * temp;
    att[2 * ddp + 1][2 * ep + 1] = a11 * ivq1 * ivk1 * temp;
    __syncthreads();

    int w = tid >> 5, l = tid & 31;
#pragma unroll
    for (int r0 = 0; r0 < 4; r0++) {
        int r = w * 4 + r0;
        float v = att[r][l];
        float m = v;
#pragma unroll
        for (int o = 16; o > 0; o >>= 1) m = fmaxf(m, __shfl_xor_sync(0xffffffffu, m, o));
        float e = fexp(v - m);
        float sum = e;
#pragma unroll
        for (int o = 16; o > 0; o >>= 1) sum += __shfl_xor_sync(0xffffffffu, sum, o);
        g_attn[bh * 1024 + r * 32 + l] = e / sum;
    }
}

// ---------------------------------------------------------------------------
// K6: combine
// ---------------------------------------------------------------------------
__global__ __launch_bounds__(128) void k6_combine(float* __restrict__ out) {
    int ch = blockIdx.x;
    int bh = blockIdx.y;
    int b = bh >> 3, h = bh & 7;
    __shared__ float vcs[32][128];
    __shared__ float sas[128][33];
    __shared__ float att[1024];
    int tid = threadIdx.x;

    const __half* vsrc = g_proj + ((size_t)5 * 2048 + bh * 32) * N_ + ch * 128;
#pragma unroll
    for (int i = 0; i < 32; i++) {
        int f = tid + i * 128;
        int e = f >> 7, j = f & 127;
        vcs[e][j] = __half2float(vsrc[(size_t)e * N_ + j]);
    }
#pragma unroll
    for (int i = 0; i < 32; i++) {
        int f = tid + i * 128;
        int tp = f >> 5, dc = f & 31;
        sas[tp][dc] = __half2float(g_xsa[((size_t)(b * 8 + (tp >> 4)) * 32 + ch) * N_ +
                                         (tp & 15) * 256 + h * 32 + dc]);
    }
#pragma unroll
    for (int i = 0; i < 8; i++) att[tid + i * 128] = g_attn[bh * 1024 + tid + i * 128];
    __syncthreads();

    float acc[32];
#pragma unroll
    for (int dc = 0; dc < 32; dc++) acc[dc] = 0.f;
#pragma unroll 4
    for (int e = 0; e < 32; e++) {
        float v = vcs[e][tid];
#pragma unroll
        for (int dc = 0; dc < 32; dc++) acc[dc] += att[dc * 32 + e] * v;
    }
    float* ob = out + (size_t)(b * 256 + h * 32) * N_ + ch * 128 + tid;
#pragma unroll
    for (int dc = 0; dc < 32; dc++) ob[(size_t)dc * N_] = acc[dc] + sas[tid][dc];
}

// ---------------------------------------------------------------------------
extern "C" void kernel_launch(void* const* d_in, const int* in_sizes, int n_in,
                              void* d_out, int out_size) {
    const float* x    = (const float*)d_in[0];
    const float* Wsa  = (const float*)d_in[1];
    const float* EF   = (const float*)d_in[2];
    const float* t2sa = (const float*)d_in[3];
    const float* Wsc  = (const float*)d_in[4];
    const float* tsc  = (const float*)d_in[5];
    float* out = (float*)d_out;

    const int k1_smem = 2 * 2 * K1_TILE_HALVES * (int)sizeof(__half);  // 40960
    cudaFuncSetAttribute(k1_mma, cudaFuncAttributeMaxDynamicSharedMemorySize, k1_smem);

    k0w_pack<<<1536, 256>>>(Wsa, Wsc);
    k0x_pack<<<dim3(32, 8), 128>>>(x);
    k1_mma<<<dim3(32, 12, 8), 256, k1_smem>>>();
    k3_kvproj<<<dim3(128, 8), 256>>>(EF);
    k3r_reduce<<<1024, 256>>>();
    k4_spatial<<<dim3(16, 64), 256>>>(t2sa);
    k5_gram<<<64, 256>>>(tsc);
    k6_combine<<<dim3(32, 64), 128>>>(out);
}

// round 10
// speedup vs baseline: 2.2266x; 1.1593x over previous
#include <cuda_runtime.h>
#include <cuda_bf16.h>
#include <cuda_fp16.h>
#include <math.h>
#include <stdint.h>

// Problem constants
#define B_ 8
#define C_ 256
#define N_ 4096
#define H_ 8
#define D_ 32
#define P_ 64

// Scratch (device globals; allocation-free contract)
// g_proj layout: [slab][b][row256][n] (fp16), slab: 0=q_sa,1=k_sa,2=v_sa,3=q_c,4=k_c,5=v_c
__device__ __half g_proj[6u * 8u * 256u * 4096u];     // 100 MB
__device__ float g_sumsq[3 * 2048];                   // row sum-of-squares (atomic)
__device__ float g_kvp[8][2 * 64 * 32 * 64];          // K-split partials [sp][row*64+p]
__device__ float g_kv[2 * 64 * 32 * 64];
__device__ float g_attn[64 * 32 * 32];
__device__ __half g_xsa[8u * 8u * 32u * 4096u];       // spatial out [b][h][d][n], fp16

// fp16 operands for the tensor-core GEMMs
__device__ __half g_Wh[1536 * 256];
__device__ __half g_xh[8u * 4096u * 256u];            // [b][n][c]  (transposed)
__device__ __half g_EFh[64 * 4096];                   // EF transposed: [p][n]

// ---------------------------------------------------------------------------
// helpers
// ---------------------------------------------------------------------------
__device__ __forceinline__ uint32_t smem_u32(const void* p) {
    uint32_t a;
    asm("{ .reg .u64 t; cvta.to.shared.u64 t, %1; cvt.u32.u64 %0, t; }" : "=r"(a) : "l"(p));
    return a;
}
#define CP_ASYNC16(dst, src) \
    asm volatile("cp.async.cg.shared.global [%0], [%1], 16;" :: "r"(dst), "l"(src))
#define CP_COMMIT() asm volatile("cp.async.commit_group;" ::: "memory")
#define CP_WAIT1()  asm volatile("cp.async.wait_group 1;" ::: "memory")

__device__ __forceinline__ void mma_f16(float* d, const uint32_t* a, const uint32_t* bb) {
    asm volatile(
        "mma.sync.aligned.m16n8k16.row.col.f32.f16.f16.f32 "
        "{%0,%1,%2,%3}, {%4,%5,%6,%7}, {%8,%9}, {%0,%1,%2,%3};"
        : "+f"(d[0]), "+f"(d[1]), "+f"(d[2]), "+f"(d[3])
        : "r"(a[0]), "r"(a[1]), "r"(a[2]), "r"(a[3]), "r"(bb[0]), "r"(bb[1]));
}

// FFMA-only exp (avoids MUFU pipe), ~2e-6 relative accuracy.
__device__ __forceinline__ float fexp(float x) {
    const float L2E = 1.4426950408889634f;
    float t = fmaf(x, L2E, 12582912.0f);
    float n = t - 12582912.0f;
    float f = fmaf(x, L2E, -n);
    float p = 1.33978035e-3f;
    p = fmaf(p, f, 9.67770915e-3f);
    p = fmaf(p, f, 5.55041086e-2f);
    p = fmaf(p, f, 2.40226507e-1f);
    p = fmaf(p, f, 6.93147182e-1f);
    p = fmaf(p, f, 1.0f);
    int e = __float2int_rn(n);
    if (e < -126) e = -126;
    if (e > 126) e = 126;
    return __int_as_float((e + 127) << 23) * p;
}

__device__ __forceinline__ float inv_norm(float ss) {
    return 1.f / fmaxf(sqrtf(ss), 1e-12f);
}

// ---------------------------------------------------------------------------
// K0w: pack weights into fp16 (GEMM row order) + zero g_sumsq.
// ---------------------------------------------------------------------------
__global__ __launch_bounds__(256) void k0w_pack(const float* __restrict__ Wsa,
                                                const float* __restrict__ Wsc) {
    int e = blockIdx.x * 256 + threadIdx.x;       // 0 .. 393215
    if (e < 3 * 2048) g_sumsq[e] = 0.f;
    int r = e >> 8, c = e & 255;
    int p = (r >= 768) ? 1 : 0;
    int rr = r - p * 768;
    int t = rr >> 8;
    const float* Wp = p ? Wsc : Wsa;
    int srow = rr + ((p == 0 && t == 2) ? 256 : 0);
    g_Wh[e] = __float2half(Wp[(size_t)srow * 256 + c]);
}

// ---------------------------------------------------------------------------
// K0x: transpose x [b][c][n] -> [b][n][c], fp16.
// ---------------------------------------------------------------------------
__global__ __launch_bounds__(128) void k0x_pack(const float* __restrict__ x) {
    int n0 = blockIdx.x * 128;
    int b = blockIdx.y;
    __shared__ float sm[64][132];
    int tid = threadIdx.x;
    const float* xb = x + (size_t)b * C_ * N_;

    for (int c0 = 0; c0 < 256; c0 += 64) {
#pragma unroll
        for (int i = 0; i < 16; i++) {
            int u = tid + i * 128;
            int c = u >> 5, nq = u & 31;
            *(float4*)&sm[c][nq * 4] =
                *(const float4*)(xb + (size_t)(c0 + c) * N_ + n0 + nq * 4);
        }
        __syncthreads();
        uint32_t buf[32];
#pragma unroll
        for (int c = 0; c < 64; c += 2) {
            __half2 hv = __floats2half2_rn(sm[c][tid], sm[c + 1][tid]);
            buf[c >> 1] = *(uint32_t*)&hv;
        }
        size_t obase = ((size_t)b * 4096 + n0 + tid) * 256 + c0;
#pragma unroll
        for (int j = 0; j < 8; j++)
            *(uint4*)&g_xh[obase + j * 8] = *(uint4*)&buf[j * 4];
        __syncthreads();
    }
}

// ---------------------------------------------------------------------------
// K0e: transpose EF [n][p] fp32 -> g_EFh [p][n] fp16.  64 blocks x 64 n.
// ---------------------------------------------------------------------------
__global__ __launch_bounds__(256) void k0e_pack(const float* __restrict__ EF) {
    __shared__ float tile[64][65];
    int n0 = blockIdx.x * 64;
    int tid = threadIdx.x;
#pragma unroll
    for (int i = 0; i < 16; i++) {
        int u = tid + i * 256;
        int r = u >> 6, c = u & 63;          // r = n local, c = p
        tile[c][r] = EF[(size_t)(n0 + r) * 64 + c];
    }
    __syncthreads();
#pragma unroll
    for (int i = 0; i < 16; i++) {
        int u = tid + i * 256;
        int p = u >> 6, j = u & 63;
        g_EFh[(size_t)p * 4096 + n0 + j] = __float2half(tile[p][j]);
    }
}

// ---------------------------------------------------------------------------
// K1: fp16 mma.sync GEMM.  D[m][n] = sum_c W[m][c] * x[b][c][n]
// CTA 128m x 128n; 8 warps (2m x 4n); 8 double-buffered k32 steps.
// ---------------------------------------------------------------------------
#define K1_TSTRIDE 40
#define K1_TILE_HALVES (128 * K1_TSTRIDE)

__global__ __launch_bounds__(256) void k1_mma() {
    extern __shared__ __half sm1[];
    const int n0 = blockIdx.x * 128;
    const int my = blockIdx.y;                  // 0..11
    const int b  = blockIdx.z;
    const int m0 = my * 128;

    const int tid = threadIdx.x;
    const int wid = tid >> 5, lane = tid & 31;
    const int wm = (wid & 1) * 64, wn = (wid >> 1) * 32;
    const int g = lane >> 2, t4 = lane & 3;

#define TILE(buf, t) (sm1 + ((buf) * 2 + (t)) * K1_TILE_HALVES)

    float acc[4][4][4];
#pragma unroll
    for (int mt = 0; mt < 4; mt++)
#pragma unroll
        for (int nt = 0; nt < 4; nt++)
#pragma unroll
            for (int j = 0; j < 4; j++) acc[mt][nt][j] = 0.f;

    const int lr0 = tid >> 2;
    const int ls0 = (tid & 3) * 8;

#define LOAD_STEP(kc, buf)                                                              \
    do {                                                                                \
        int _k0 = (kc) * 32;                                                            \
        const __half* _A = g_Wh + (size_t)m0 * 256 + _k0;                               \
        const __half* _B = g_xh + ((size_t)b * 4096 + n0) * 256 + _k0;                  \
        CP_ASYNC16(smem_u32(TILE(buf,0) + lr0 * K1_TSTRIDE + ls0), _A + (size_t)lr0 * 256 + ls0); \
        CP_ASYNC16(smem_u32(TILE(buf,0) + (lr0+64) * K1_TSTRIDE + ls0), _A + (size_t)(lr0+64) * 256 + ls0); \
        CP_ASYNC16(smem_u32(TILE(buf,1) + lr0 * K1_TSTRIDE + ls0), _B + (size_t)lr0 * 256 + ls0); \
        CP_ASYNC16(smem_u32(TILE(buf,1) + (lr0+64) * K1_TSTRIDE + ls0), _B + (size_t)(lr0+64) * 256 + ls0); \
    } while (0)

    LOAD_STEP(0, 0); CP_COMMIT();
    LOAD_STEP(1, 1); CP_COMMIT();

    for (int s = 0; s < 8; s++) {
        const int buf = s & 1;
        CP_WAIT1();
        __syncthreads();

#pragma unroll
        for (int h = 0; h < 2; h++) {
            uint32_t af[4][4], bfr[4][2];
#pragma unroll
            for (int mt = 0; mt < 4; mt++) {
                const __half* base = TILE(buf,0) + (wm + mt * 16 + g) * K1_TSTRIDE + h * 16;
                af[mt][0] = *(const uint32_t*)(base + 2 * t4);
                af[mt][1] = *(const uint32_t*)(base + 8 * K1_TSTRIDE + 2 * t4);
                af[mt][2] = *(const uint32_t*)(base + 2 * t4 + 8);
                af[mt][3] = *(const uint32_t*)(base + 8 * K1_TSTRIDE + 2 * t4 + 8);
            }
#pragma unroll
            for (int nt = 0; nt < 4; nt++) {
                const __half* nb = TILE(buf,1) + (wn + nt * 8 + g) * K1_TSTRIDE + h * 16;
                bfr[nt][0] = *(const uint32_t*)(nb + 2 * t4);
                bfr[nt][1] = *(const uint32_t*)(nb + 2 * t4 + 8);
            }
#pragma unroll
            for (int mt = 0; mt < 4; mt++)
#pragma unroll
                for (int nt = 0; nt < 4; nt++)
                    mma_f16(acc[mt][nt], af[mt], bfr[nt]);
        }

        __syncthreads();
        if (s + 2 < 8) LOAD_STEP(s + 2, buf);
        CP_COMMIT();
    }
#undef LOAD_STEP
#undef TILE

    // epilogue -> g_proj (fp16) + fused sumsq for slabs 0,3,4
    const int slab = my >> 1;
    const int rb = (my & 1) * 128;
    const int which = (slab == 0) ? 0 : (slab == 3 ? 1 : (slab == 4 ? 2 : -1));
#pragma unroll
    for (int mt = 0; mt < 4; mt++) {
        int r0 = rb + wm + mt * 16 + g;
        __half* p0 = g_proj + (((size_t)slab * 8 + b) * 256 + r0) * (size_t)N_ + n0 + wn;
        __half* p1 = p0 + 8 * (size_t)N_;
        float ss0 = 0.f, ss1 = 0.f;
#pragma unroll
        for (int nt = 0; nt < 4; nt++) {
            float a0 = acc[mt][nt][0], a1 = acc[mt][nt][1];
            float a2 = acc[mt][nt][2], a3 = acc[mt][nt][3];
            *(__half2*)(p0 + nt * 8 + 2 * t4) = __floats2half2_rn(a0, a1);
            *(__half2*)(p1 + nt * 8 + 2 * t4) = __floats2half2_rn(a2, a3);
            ss0 += a0 * a0 + a1 * a1;
            ss1 += a2 * a2 + a3 * a3;
        }
        if (which >= 0) {
            ss0 += __shfl_xor_sync(0xffffffffu, ss0, 1);
            ss0 += __shfl_xor_sync(0xffffffffu, ss0, 2);
            ss1 += __shfl_xor_sync(0xffffffffu, ss1, 1);
            ss1 += __shfl_xor_sync(0xffffffffu, ss1, 2);
            if (t4 == 0) {
                int row = b * 256 + r0;
                atomicAdd(&g_sumsq[which * 2048 + row], ss0);
                atomicAdd(&g_sumsq[which * 2048 + row + 8], ss1);
            }
        }
    }
}

// ---------------------------------------------------------------------------
// K3: Linformer projection as ONE tensor-core GEMM.
// A = g_proj slabs 1,2 (rows 2048..6143) [4096 x 4096] fp16 (K-contiguous)
// B = g_EFh [64 p x 4096 n] fp16 (K-contiguous) -> C[row][p] partials (K-split 8)
// CTA 128m x 64n; 8 warps (4m x 2n); 16 double-buffered k32 steps (K=512/split).
// ---------------------------------------------------------------------------
#define K3_STRIDE 40
__global__ __launch_bounds__(256) void k3_mma() {
    __shared__ __half As[2][128][K3_STRIDE];
    __shared__ __half Bs[2][64][K3_STRIDE];
    const int m0 = blockIdx.x * 128;
    const int sp = blockIdx.y;
    const int kb = sp * 512;

    const int tid = threadIdx.x;
    const int wid = tid >> 5, lane = tid & 31;
    const int wm = (wid >> 1) * 32;              // 4 m-warps
    const int wn = (wid & 1) * 32;               // 2 n-warps
    const int g = lane >> 2, t4 = lane & 3;

    const __half* Ag = g_proj + (size_t)2048 * N_;   // GEMM A base

    float acc[2][4][4];
#pragma unroll
    for (int mt = 0; mt < 2; mt++)
#pragma unroll
        for (int nt = 0; nt < 4; nt++)
#pragma unroll
            for (int j = 0; j < 4; j++) acc[mt][nt][j] = 0.f;

    const int lr = tid >> 2;                     // 0..63
    const int ls = (tid & 3) * 8;

#define K3_LOAD(kc, buf)                                                                \
    do {                                                                                \
        int _k0 = kb + (kc) * 32;                                                       \
        const __half* _A = Ag + (size_t)m0 * 4096 + _k0;                                \
        const __half* _B = g_EFh + _k0;                                                 \
        CP_ASYNC16(smem_u32(&As[buf][lr][ls]), _A + (size_t)lr * 4096 + ls);            \
        CP_ASYNC16(smem_u32(&As[buf][lr + 64][ls]), _A + (size_t)(lr + 64) * 4096 + ls);\
        CP_ASYNC16(smem_u32(&Bs[buf][lr][ls]), _B + (size_t)lr * 4096 + ls);            \
    } while (0)

    K3_LOAD(0, 0); CP_COMMIT();
    K3_LOAD(1, 1); CP_COMMIT();

    for (int s = 0; s < 16; s++) {
        const int buf = s & 1;
        CP_WAIT1();
        __syncthreads();

#pragma unroll
        for (int h = 0; h < 2; h++) {
            uint32_t af[2][4], bfr[4][2];
#pragma unroll
            for (int mt = 0; mt < 2; mt++) {
                const __half* base = &As[buf][wm + mt * 16 + g][h * 16];
                af[mt][0] = *(const uint32_t*)(base + 2 * t4);
                af[mt][1] = *(const uint32_t*)(base + 8 * K3_STRIDE + 2 * t4);
                af[mt][2] = *(const uint32_t*)(base + 2 * t4 + 8);
                af[mt][3] = *(const uint32_t*)(base + 8 * K3_STRIDE + 2 * t4 + 8);
            }
#pragma unroll
            for (int nt = 0; nt < 4; nt++) {
                const __half* nb = &Bs[buf][wn + nt * 8 + g][h * 16];
                bfr[nt][0] = *(const uint32_t*)(nb + 2 * t4);
                bfr[nt][1] = *(const uint32_t*)(nb + 2 * t4 + 8);
            }
#pragma unroll
            for (int mt = 0; mt < 2; mt++)
#pragma unroll
                for (int nt = 0; nt < 4; nt++)
                    mma_f16(acc[mt][nt], af[mt], bfr[nt]);
        }

        __syncthreads();
        if (s + 2 < 16) K3_LOAD(s + 2, buf);
        CP_COMMIT();
    }
#undef K3_LOAD

    // epilogue -> g_kvp[sp][row*64 + p]
#pragma unroll
    for (int mt = 0; mt < 2; mt++) {
        int row = m0 + wm + mt * 16 + g;
        float* p0 = &g_kvp[sp][(size_t)row * 64 + wn];
        float* p1 = p0 + 8 * 64;
#pragma unroll
        for (int nt = 0; nt < 4; nt++) {
            *(float2*)(p0 + nt * 8 + 2 * t4) = make_float2(acc[mt][nt][0], acc[mt][nt][1]);
            *(float2*)(p1 + nt * 8 + 2 * t4) = make_float2(acc[mt][nt][2], acc[mt][nt][3]);
        }
    }
}

__global__ __launch_bounds__(256) void k3r_reduce() {
    int i = blockIdx.x * 256 + threadIdx.x;
    float s = 0.f;
#pragma unroll
    for (int sp = 0; sp < 8; sp++) s += g_kvp[sp][i];
    g_kv[i] = s;
}

// ---------------------------------------------------------------------------
// K4: spatial attention (inline inverse norms)
// ---------------------------------------------------------------------------
__global__ __launch_bounds__(256) void k4_spatial(const float* __restrict__ temp2_sa) {
    int ch = blockIdx.x, bh = blockIdx.y;
    int h = bh & 7;
    __shared__ float Ks[32][64], Vs[32][64];
    __shared__ float ivs[32];
    int tid = threadIdx.x;
    float* ksf = &Ks[0][0];
    float* vsf = &Vs[0][0];
    for (int i = tid; i < 2048; i += 256) {
        ksf[i] = g_kv[(0 * 64 + bh) * 2048 + i];
        vsf[i] = g_kv[(1 * 64 + bh) * 2048 + i];
    }
    if (tid < 32) ivs[tid] = inv_norm(g_sumsq[bh * 32 + tid]);
    __syncthreads();

    int n = ch * 256 + tid;
    const __half* qb = g_proj + (size_t)(bh * 32) * N_ + n;
    float temp = temp2_sa[h];

    float qn[32];
#pragma unroll
    for (int d = 0; d < 32; d++) qn[d] = __half2float(qb[(size_t)d * N_]) * ivs[d];

    float s[64];
#pragma unroll
    for (int j = 0; j < 64; j++) s[j] = 0.f;
#pragma unroll
    for (int d = 0; d < 32; d++) {
        float q = qn[d];
#pragma unroll
        for (int pq = 0; pq < 16; pq++) {
            float4 k4 = *(const float4*)&Ks[d][pq * 4];
            s[pq * 4 + 0] += q * k4.x;
            s[pq * 4 + 1] += q * k4.y;
            s[pq * 4 + 2] += q * k4.z;
            s[pq * 4 + 3] += q * k4.w;
        }
    }
    float mx = -1e30f;
#pragma unroll
    for (int j = 0; j < 64; j++) { s[j] *= temp; mx = fmaxf(mx, s[j]); }
    float sum = 0.f;
#pragma unroll
    for (int j = 0; j < 64; j++) { float e = fexp(s[j] - mx); s[j] = e; sum += e; }
    float isum = 1.f / sum;

    __half* ob = g_xsa + (size_t)(bh * 32) * N_ + n;
#pragma unroll
    for (int d = 0; d < 32; d++) {
        float o = 0.f;
#pragma unroll
        for (int pq = 0; pq < 16; pq++) {
            float4 v4 = *(const float4*)&Vs[d][pq * 4];
            o += s[pq * 4 + 0] * v4.x + s[pq * 4 + 1] * v4.y +
                 s[pq * 4 + 2] * v4.z + s[pq * 4 + 3] * v4.w;
        }
        ob[(size_t)d * N_] = __float2half(o * isum);
    }
}

// ---------------------------------------------------------------------------
// K5: channel gram + softmax (inline inverse norms)
// ---------------------------------------------------------------------------
__global__ __launch_bounds__(256) void k5_gram(const float* __restrict__ temp_sc) {
    int bh = blockIdx.x;
    int h = bh & 7;
    __shared__ float qcs[32][133], kcs[32][133];
    __shared__ float att[32][33];
    int tid = threadIdx.x;
    int ddp = tid >> 4, ep = tid & 15;
    float a00 = 0.f, a01 = 0.f, a10 = 0.f, a11 = 0.f;
    const __half* qsrc = g_proj + ((size_t)3 * 2048 + bh * 32) * N_;
    const __half* ksrc = g_proj + ((size_t)4 * 2048 + bh * 32) * N_;

    for (int c0 = 0; c0 < N_; c0 += 128) {
#pragma unroll
        for (int i = 0; i < 16; i++) {
            int f = tid + i * 256;
            int r = f >> 7, j = f & 127;
            qcs[r][j] = __half2float(qsrc[(size_t)r * N_ + c0 + j]);
            kcs[r][j] = __half2float(ksrc[(size_t)r * N_ + c0 + j]);
        }
        __syncthreads();
#pragma unroll 4
        for (int nn = 0; nn < 128; nn++) {
            float q0 = qcs[2 * ddp][nn], q1 = qcs[2 * ddp + 1][nn];
            float k0 = kcs[2 * ep][nn],  k1 = kcs[2 * ep + 1][nn];
            a00 += q0 * k0; a01 += q0 * k1;
            a10 += q1 * k0; a11 += q1 * k1;
        }
        __syncthreads();
    }
    float temp = temp_sc[h];
    float ivq0 = inv_norm(g_sumsq[2048 + bh * 32 + 2 * ddp]);
    float ivq1 = inv_norm(g_sumsq[2048 + bh * 32 + 2 * ddp + 1]);
    float ivk0 = inv_norm(g_sumsq[4096 + bh * 32 + 2 * ep]);
    float ivk1 = inv_norm(g_sumsq[4096 + bh * 32 + 2 * ep + 1]);
    att[2 * ddp][2 * ep]         = a00 * ivq0 * ivk0 * temp;
    att[2 * ddp][2 * ep + 1]     = a01 * ivq0 * ivk1 * temp;
    att[2 * ddp + 1][2 * ep]     = a10 * ivq1 * ivk0 * temp;
    att[2 * ddp + 1][2 * ep + 1] = a11 * ivq1 * ivk1 * temp;
    __syncthreads();

    int w = tid >> 5, l = tid & 31;
#pragma unroll
    for (int r0 = 0; r0 < 4; r0++) {
        int r = w * 4 + r0;
        float v = att[r][l];
        float m = v;
#pragma unroll
        for (int o = 16; o > 0; o >>= 1) m = fmaxf(m, __shfl_xor_sync(0xffffffffu, m, o));
        float e = fexp(v - m);
        float sum = e;
#pragma unroll
        for (int o = 16; o > 0; o >>= 1) sum += __shfl_xor_sync(0xffffffffu, sum, o);
        g_attn[bh * 1024 + r * 32 + l] = e / sum;
    }
}

// ---------------------------------------------------------------------------
// K6: combine
// ---------------------------------------------------------------------------
__global__ __launch_bounds__(128) void k6_combine(float* __restrict__ out) {
    int ch = blockIdx.x;
    int bh = blockIdx.y;
    int b = bh >> 3, h = bh & 7;
    __shared__ float vcs[32][128];
    __shared__ float sas[128][33];
    __shared__ float att[1024];
    int tid = threadIdx.x;

    const __half* vsrc = g_proj + ((size_t)5 * 2048 + bh * 32) * N_ + ch * 128;
#pragma unroll
    for (int i = 0; i < 32; i++) {
        int f = tid + i * 128;
        int e = f >> 7, j = f & 127;
        vcs[e][j] = __half2float(vsrc[(size_t)e * N_ + j]);
    }
#pragma unroll
    for (int i = 0; i < 32; i++) {
        int f = tid + i * 128;
        int tp = f >> 5, dc = f & 31;
        sas[tp][dc] = __half2float(g_xsa[((size_t)(b * 8 + (tp >> 4)) * 32 + ch) * N_ +
                                         (tp & 15) * 256 + h * 32 + dc]);
    }
#pragma unroll
    for (int i = 0; i < 8; i++) att[tid + i * 128] = g_attn[bh * 1024 + tid + i * 128];
    __syncthreads();

    float acc[32];
#pragma unroll
    for (int dc = 0; dc < 32; dc++) acc[dc] = 0.f;
#pragma unroll 4
    for (int e = 0; e < 32; e++) {
        float v = vcs[e][tid];
#pragma unroll
        for (int dc = 0; dc < 32; dc++) acc[dc] += att[dc * 32 + e] * v;
    }
    float* ob = out + (size_t)(b * 256 + h * 32) * N_ + ch * 128 + tid;
#pragma unroll
    for (int dc = 0; dc < 32; dc++) ob[(size_t)dc * N_] = acc[dc] + sas[tid][dc];
}

// ---------------------------------------------------------------------------
extern "C" void kernel_launch(void* const* d_in, const int* in_sizes, int n_in,
                              void* d_out, int out_size) {
    const float* x    = (const float*)d_in[0];
    const float* Wsa  = (const float*)d_in[1];
    const float* EF   = (const float*)d_in[2];
    const float* t2sa = (const float*)d_in[3];
    const float* Wsc  = (const float*)d_in[4];
    const float* tsc  = (const float*)d_in[5];
    float* out = (float*)d_out;

    const int k1_smem = 2 * 2 * K1_TILE_HALVES * (int)sizeof(__half);  // 40960
    cudaFuncSetAttribute(k1_mma, cudaFuncAttributeMaxDynamicSharedMemorySize, k1_smem);

    k0w_pack<<<1536, 256>>>(Wsa, Wsc);
    k0x_pack<<<dim3(32, 8), 128>>>(x);
    k0e_pack<<<64, 256>>>(EF);
    k1_mma<<<dim3(32, 12, 8), 256, k1_smem>>>();
    k3_mma<<<dim3(32, 8), 256>>>();
    k3r_reduce<<<1024, 256>>>();
    k4_spatial<<<dim3(16, 64), 256>>>(t2sa);
    k5_gram<<<64, 256>>>(tsc);
    k6_combine<<<dim3(32, 64), 128>>>(out);
}

// round 11
// speedup vs baseline: 2.9836x; 1.3400x over previous
#include <cuda_runtime.h>
#include <cuda_bf16.h>
#include <cuda_fp16.h>
#include <math.h>
#include <stdint.h>

// Problem constants
#define B_ 8
#define C_ 256
#define N_ 4096
#define H_ 8
#define D_ 32
#define P_ 64

// Scratch (device globals; allocation-free contract)
// g_proj layout: [slab][b][row256][n] (fp16), slab: 0=q_sa,1=k_sa,2=v_sa,3=q_c,4=k_c,5=v_c
__device__ __half g_proj[6u * 8u * 256u * 4096u];     // 100 MB
__device__ float g_sumsq[3 * 2048];                   // row sum-of-squares (atomic)
__device__ float g_kvp[8][2 * 64 * 32 * 64];          // K-split partials [sp][row*64+p]
__device__ float g_kv[2 * 64 * 32 * 64];
__device__ float g_gram[64 * 32 * 32];                // channel gram partial sums (atomic)
__device__ float g_attn[64 * 32 * 32];
__device__ __half g_xsa[8u * 8u * 32u * 4096u];       // spatial out [b][h][d][n], fp16

// fp16 operands for the tensor-core GEMMs
__device__ __half g_Wh[1536 * 256];
__device__ __half g_xh[8u * 4096u * 256u];            // [b][n][c]  (transposed)
__device__ __half g_EFh[64 * 4096];                   // EF transposed: [p][n]

// ---------------------------------------------------------------------------
// helpers
// ---------------------------------------------------------------------------
__device__ __forceinline__ uint32_t smem_u32(const void* p) {
    uint32_t a;
    asm("{ .reg .u64 t; cvta.to.shared.u64 t, %1; cvt.u32.u64 %0, t; }" : "=r"(a) : "l"(p));
    return a;
}
#define CP_ASYNC16(dst, src) \
    asm volatile("cp.async.cg.shared.global [%0], [%1], 16;" :: "r"(dst), "l"(src))
#define CP_COMMIT() asm volatile("cp.async.commit_group;" ::: "memory")
#define CP_WAITG1() asm volatile("cp.async.wait_group 1;" ::: "memory")

__device__ __forceinline__ void mma_f16(float* d, const uint32_t* a, const uint32_t* bb) {
    asm volatile(
        "mma.sync.aligned.m16n8k16.row.col.f32.f16.f16.f32 "
        "{%0,%1,%2,%3}, {%4,%5,%6,%7}, {%8,%9}, {%0,%1,%2,%3};"
        : "+f"(d[0]), "+f"(d[1]), "+f"(d[2]), "+f"(d[3])
        : "r"(a[0]), "r"(a[1]), "r"(a[2]), "r"(a[3]), "r"(bb[0]), "r"(bb[1]));
}
__device__ __forceinline__ void ldsm_x4(uint32_t& r0, uint32_t& r1, uint32_t& r2,
                                        uint32_t& r3, uint32_t addr) {
    asm volatile("ldmatrix.sync.aligned.m8n8.x4.shared.b16 {%0,%1,%2,%3}, [%4];"
                 : "=r"(r0), "=r"(r1), "=r"(r2), "=r"(r3) : "r"(addr));
}
__device__ __forceinline__ void ldsm_x2(uint32_t& r0, uint32_t& r1, uint32_t addr) {
    asm volatile("ldmatrix.sync.aligned.m8n8.x2.shared.b16 {%0,%1}, [%2];"
                 : "=r"(r0), "=r"(r1) : "r"(addr));
}

// FFMA-only exp (avoids MUFU pipe), ~2e-6 relative accuracy.
__device__ __forceinline__ float fexp(float x) {
    const float L2E = 1.4426950408889634f;
    float t = fmaf(x, L2E, 12582912.0f);
    float n = t - 12582912.0f;
    float f = fmaf(x, L2E, -n);
    float p = 1.33978035e-3f;
    p = fmaf(p, f, 9.67770915e-3f);
    p = fmaf(p, f, 5.55041086e-2f);
    p = fmaf(p, f, 2.40226507e-1f);
    p = fmaf(p, f, 6.93147182e-1f);
    p = fmaf(p, f, 1.0f);
    int e = __float2int_rn(n);
    if (e < -126) e = -126;
    if (e > 126) e = 126;
    return __int_as_float((e + 127) << 23) * p;
}

__device__ __forceinline__ float inv_norm(float ss) {
    return 1.f / fmaxf(sqrtf(ss), 1e-12f);
}

// ---------------------------------------------------------------------------
// K0w: pack weights into fp16 (GEMM row order) + zero accumulators.
// ---------------------------------------------------------------------------
__global__ __launch_bounds__(256) void k0w_pack(const float* __restrict__ Wsa,
                                                const float* __restrict__ Wsc) {
    int e = blockIdx.x * 256 + threadIdx.x;       // 0 .. 393215
    if (e < 3 * 2048) g_sumsq[e] = 0.f;
    if (e < 64 * 32 * 32) g_gram[e] = 0.f;
    int r = e >> 8, c = e & 255;
    int p = (r >= 768) ? 1 : 0;
    int rr = r - p * 768;
    int t = rr >> 8;
    const float* Wp = p ? Wsc : Wsa;
    int srow = rr + ((p == 0 && t == 2) ? 256 : 0);
    g_Wh[e] = __float2half(Wp[(size_t)srow * 256 + c]);
}

// ---------------------------------------------------------------------------
// K0x: transpose x [b][c][n] -> [b][n][c], fp16.
// ---------------------------------------------------------------------------
__global__ __launch_bounds__(128) void k0x_pack(const float* __restrict__ x) {
    int n0 = blockIdx.x * 128;
    int b = blockIdx.y;
    __shared__ float sm[64][132];
    int tid = threadIdx.x;
    const float* xb = x + (size_t)b * C_ * N_;

    for (int c0 = 0; c0 < 256; c0 += 64) {
#pragma unroll
        for (int i = 0; i < 16; i++) {
            int u = tid + i * 128;
            int c = u >> 5, nq = u & 31;
            *(float4*)&sm[c][nq * 4] =
                *(const float4*)(xb + (size_t)(c0 + c) * N_ + n0 + nq * 4);
        }
        __syncthreads();
        uint32_t buf[32];
#pragma unroll
        for (int c = 0; c < 64; c += 2) {
            __half2 hv = __floats2half2_rn(sm[c][tid], sm[c + 1][tid]);
            buf[c >> 1] = *(uint32_t*)&hv;
        }
        size_t obase = ((size_t)b * 4096 + n0 + tid) * 256 + c0;
#pragma unroll
        for (int j = 0; j < 8; j++)
            *(uint4*)&g_xh[obase + j * 8] = *(uint4*)&buf[j * 4];
        __syncthreads();
    }
}

// ---------------------------------------------------------------------------
// K0e: transpose EF [n][p] fp32 -> g_EFh [p][n] fp16.
// ---------------------------------------------------------------------------
__global__ __launch_bounds__(256) void k0e_pack(const float* __restrict__ EF) {
    __shared__ float tile[64][65];
    int n0 = blockIdx.x * 64;
    int tid = threadIdx.x;
#pragma unroll
    for (int i = 0; i < 16; i++) {
        int u = tid + i * 256;
        int r = u >> 6, c = u & 63;
        tile[c][r] = EF[(size_t)(n0 + r) * 64 + c];
    }
    __syncthreads();
#pragma unroll
    for (int i = 0; i < 16; i++) {
        int u = tid + i * 256;
        int p = u >> 6, j = u & 63;
        g_EFh[(size_t)p * 4096 + n0 + j] = __float2half(tile[p][j]);
    }
}

// ---------------------------------------------------------------------------
// K1: fp16 mma.sync GEMM with ldmatrix + 3-stage cp.async pipeline.
// CTA 128m x 128n; 8 warps (2m x 4n); 8 k32 steps.
// ---------------------------------------------------------------------------
#define K1_TSTRIDE 40
#define K1_TILE_HALVES (128 * K1_TSTRIDE)

__global__ __launch_bounds__(256) void k1_mma() {
    extern __shared__ __half sm1[];
    const int n0 = blockIdx.x * 128;
    const int my = blockIdx.y;                  // 0..11
    const int b  = blockIdx.z;
    const int m0 = my * 128;

    const int tid = threadIdx.x;
    const int wid = tid >> 5, lane = tid & 31;
    const int wm = (wid & 1) * 64, wn = (wid >> 1) * 32;
    const int g = lane >> 2, t4 = lane & 3;

    // ldmatrix per-lane source coordinates
    const int a_row = lane & 15, a_col = (lane >> 4) * 8;
    const int b_row = lane & 7,  b_col = ((lane >> 3) & 1) * 8;

#define TILE(buf, t) (sm1 + ((buf) * 2 + (t)) * K1_TILE_HALVES)

    float acc[4][4][4];
#pragma unroll
    for (int mt = 0; mt < 4; mt++)
#pragma unroll
        for (int nt = 0; nt < 4; nt++)
#pragma unroll
            for (int j = 0; j < 4; j++) acc[mt][nt][j] = 0.f;

    const int lr0 = tid >> 2;
    const int ls0 = (tid & 3) * 8;

#define LOAD_STEP(kc, buf)                                                              \
    do {                                                                                \
        int _k0 = (kc) * 32;                                                            \
        const __half* _A = g_Wh + (size_t)m0 * 256 + _k0;                               \
        const __half* _B = g_xh + ((size_t)b * 4096 + n0) * 256 + _k0;                  \
        CP_ASYNC16(smem_u32(TILE(buf,0) + lr0 * K1_TSTRIDE + ls0), _A + (size_t)lr0 * 256 + ls0); \
        CP_ASYNC16(smem_u32(TILE(buf,0) + (lr0+64) * K1_TSTRIDE + ls0), _A + (size_t)(lr0+64) * 256 + ls0); \
        CP_ASYNC16(smem_u32(TILE(buf,1) + lr0 * K1_TSTRIDE + ls0), _B + (size_t)lr0 * 256 + ls0); \
        CP_ASYNC16(smem_u32(TILE(buf,1) + (lr0+64) * K1_TSTRIDE + ls0), _B + (size_t)(lr0+64) * 256 + ls0); \
    } while (0)

    LOAD_STEP(0, 0); CP_COMMIT();
    LOAD_STEP(1, 1); CP_COMMIT();

    for (int s = 0; s < 8; s++) {
        const int buf = s % 3;
        CP_WAITG1();
        __syncthreads();

#pragma unroll
        for (int h = 0; h < 2; h++) {
            uint32_t af[4][4], bfr[4][2];
            const __half* Abase = TILE(buf, 0) + (size_t)a_row * K1_TSTRIDE + h * 16 + a_col;
            const __half* Bbase = TILE(buf, 1) + (size_t)b_row * K1_TSTRIDE + h * 16 + b_col;
#pragma unroll
            for (int mt = 0; mt < 4; mt++)
                ldsm_x4(af[mt][0], af[mt][1], af[mt][2], af[mt][3],
                        smem_u32(Abase + (wm + mt * 16) * K1_TSTRIDE));
#pragma unroll
            for (int nt = 0; nt < 4; nt++)
                ldsm_x2(bfr[nt][0], bfr[nt][1],
                        smem_u32(Bbase + (wn + nt * 8) * K1_TSTRIDE));
#pragma unroll
            for (int mt = 0; mt < 4; mt++)
#pragma unroll
                for (int nt = 0; nt < 4; nt++)
                    mma_f16(acc[mt][nt], af[mt], bfr[nt]);
        }

        if (s + 2 < 8) LOAD_STEP(s + 2, (s + 2) % 3);
        CP_COMMIT();
    }
#undef LOAD_STEP
#undef TILE

    // epilogue -> g_proj (fp16) + fused sumsq for slabs 0,3,4
    const int slab = my >> 1;
    const int rb = (my & 1) * 128;
    const int which = (slab == 0) ? 0 : (slab == 3 ? 1 : (slab == 4 ? 2 : -1));
#pragma unroll
    for (int mt = 0; mt < 4; mt++) {
        int r0 = rb + wm + mt * 16 + g;
        __half* p0 = g_proj + (((size_t)slab * 8 + b) * 256 + r0) * (size_t)N_ + n0 + wn;
        __half* p1 = p0 + 8 * (size_t)N_;
        float ss0 = 0.f, ss1 = 0.f;
#pragma unroll
        for (int nt = 0; nt < 4; nt++) {
            float a0 = acc[mt][nt][0], a1 = acc[mt][nt][1];
            float a2 = acc[mt][nt][2], a3 = acc[mt][nt][3];
            *(__half2*)(p0 + nt * 8 + 2 * t4) = __floats2half2_rn(a0, a1);
            *(__half2*)(p1 + nt * 8 + 2 * t4) = __floats2half2_rn(a2, a3);
            ss0 += a0 * a0 + a1 * a1;
            ss1 += a2 * a2 + a3 * a3;
        }
        if (which >= 0) {
            ss0 += __shfl_xor_sync(0xffffffffu, ss0, 1);
            ss0 += __shfl_xor_sync(0xffffffffu, ss0, 2);
            ss1 += __shfl_xor_sync(0xffffffffu, ss1, 1);
            ss1 += __shfl_xor_sync(0xffffffffu, ss1, 2);
            if (t4 == 0) {
                int row = b * 256 + r0;
                atomicAdd(&g_sumsq[which * 2048 + row], ss0);
                atomicAdd(&g_sumsq[which * 2048 + row + 8], ss1);
            }
        }
    }
}

// ---------------------------------------------------------------------------
// K3: Linformer projection GEMM with ldmatrix + 3-stage pipeline.
// A = g_proj slabs 1,2 [4096 x 4096] fp16; B = g_EFh [64 x 4096] fp16.
// CTA 128m x 64n; 8 warps (4m x 2n); 16 k32 steps; K-split 8.
// ---------------------------------------------------------------------------
#define K3_STRIDE 40
__global__ __launch_bounds__(256) void k3_mma() {
    __shared__ __half As[3][128][K3_STRIDE];
    __shared__ __half Bs[3][64][K3_STRIDE];
    const int m0 = blockIdx.x * 128;
    const int sp = blockIdx.y;
    const int kb = sp * 512;

    const int tid = threadIdx.x;
    const int wid = tid >> 5, lane = tid & 31;
    const int wm = (wid >> 1) * 32;
    const int wn = (wid & 1) * 32;
    const int g = lane >> 2, t4 = lane & 3;

    const int a_row = lane & 15, a_col = (lane >> 4) * 8;
    const int b_row = lane & 7,  b_col = ((lane >> 3) & 1) * 8;

    const __half* Ag = g_proj + (size_t)2048 * N_;

    float acc[2][4][4];
#pragma unroll
    for (int mt = 0; mt < 2; mt++)
#pragma unroll
        for (int nt = 0; nt < 4; nt++)
#pragma unroll
            for (int j = 0; j < 4; j++) acc[mt][nt][j] = 0.f;

    const int lr = tid >> 2;
    const int ls = (tid & 3) * 8;

#define K3_LOAD(kc, buf)                                                                \
    do {                                                                                \
        int _k0 = kb + (kc) * 32;                                                       \
        const __half* _A = Ag + (size_t)m0 * 4096 + _k0;                                \
        const __half* _B = g_EFh + _k0;                                                 \
        CP_ASYNC16(smem_u32(&As[buf][lr][ls]), _A + (size_t)lr * 4096 + ls);            \
        CP_ASYNC16(smem_u32(&As[buf][lr + 64][ls]), _A + (size_t)(lr + 64) * 4096 + ls);\
        CP_ASYNC16(smem_u32(&Bs[buf][lr][ls]), _B + (size_t)lr * 4096 + ls);            \
    } while (0)

    K3_LOAD(0, 0); CP_COMMIT();
    K3_LOAD(1, 1); CP_COMMIT();

    for (int s = 0; s < 16; s++) {
        const int buf = s % 3;
        CP_WAITG1();
        __syncthreads();

#pragma unroll
        for (int h = 0; h < 2; h++) {
            uint32_t af[2][4], bfr[4][2];
            const __half* Abase = &As[buf][a_row][h * 16 + a_col];
            const __half* Bbase = &Bs[buf][b_row][h * 16 + b_col];
#pragma unroll
            for (int mt = 0; mt < 2; mt++)
                ldsm_x4(af[mt][0], af[mt][1], af[mt][2], af[mt][3],
                        smem_u32(Abase + (wm + mt * 16) * K3_STRIDE));
#pragma unroll
            for (int nt = 0; nt < 4; nt++)
                ldsm_x2(bfr[nt][0], bfr[nt][1],
                        smem_u32(Bbase + (wn + nt * 8) * K3_STRIDE));
#pragma unroll
            for (int mt = 0; mt < 2; mt++)
#pragma unroll
                for (int nt = 0; nt < 4; nt++)
                    mma_f16(acc[mt][nt], af[mt], bfr[nt]);
        }

        if (s + 2 < 16) K3_LOAD(s + 2, (s + 2) % 3);
        CP_COMMIT();
    }
#undef K3_LOAD

    // epilogue -> g_kvp[sp][row*64 + p]
#pragma unroll
    for (int mt = 0; mt < 2; mt++) {
        int row = m0 + wm + mt * 16 + g;
        float* p0 = &g_kvp[sp][(size_t)row * 64 + wn];
        float* p1 = p0 + 8 * 64;
#pragma unroll
        for (int nt = 0; nt < 4; nt++) {
            *(float2*)(p0 + nt * 8 + 2 * t4) = make_float2(acc[mt][nt][0], acc[mt][nt][1]);
            *(float2*)(p1 + nt * 8 + 2 * t4) = make_float2(acc[mt][nt][2], acc[mt][nt][3]);
        }
    }
}

__global__ __launch_bounds__(256) void k3r_reduce() {
    int i = blockIdx.x * 256 + threadIdx.x;
    float s = 0.f;
#pragma unroll
    for (int sp = 0; sp < 8; sp++) s += g_kvp[sp][i];
    g_kv[i] = s;
}

// ---------------------------------------------------------------------------
// K4: spatial attention (inline inverse norms)
// ---------------------------------------------------------------------------
__global__ __launch_bounds__(256) void k4_spatial(const float* __restrict__ temp2_sa) {
    int ch = blockIdx.x, bh = blockIdx.y;
    int h = bh & 7;
    __shared__ float Ks[32][64], Vs[32][64];
    __shared__ float ivs[32];
    int tid = threadIdx.x;
    float* ksf = &Ks[0][0];
    float* vsf = &Vs[0][0];
    for (int i = tid; i < 2048; i += 256) {
        ksf[i] = g_kv[(0 * 64 + bh) * 2048 + i];
        vsf[i] = g_kv[(1 * 64 + bh) * 2048 + i];
    }
    if (tid < 32) ivs[tid] = inv_norm(g_sumsq[bh * 32 + tid]);
    __syncthreads();

    int n = ch * 256 + tid;
    const __half* qb = g_proj + (size_t)(bh * 32) * N_ + n;
    float temp = temp2_sa[h];

    float qn[32];
#pragma unroll
    for (int d = 0; d < 32; d++) qn[d] = __half2float(qb[(size_t)d * N_]) * ivs[d];

    float s[64];
#pragma unroll
    for (int j = 0; j < 64; j++) s[j] = 0.f;
#pragma unroll
    for (int d = 0; d < 32; d++) {
        float q = qn[d];
#pragma unroll
        for (int pq = 0; pq < 16; pq++) {
            float4 k4 = *(const float4*)&Ks[d][pq * 4];
            s[pq * 4 + 0] += q * k4.x;
            s[pq * 4 + 1] += q * k4.y;
            s[pq * 4 + 2] += q * k4.z;
            s[pq * 4 + 3] += q * k4.w;
        }
    }
    float mx = -1e30f;
#pragma unroll
    for (int j = 0; j < 64; j++) { s[j] *= temp; mx = fmaxf(mx, s[j]); }
    float sum = 0.f;
#pragma unroll
    for (int j = 0; j < 64; j++) { float e = fexp(s[j] - mx); s[j] = e; sum += e; }
    float isum = 1.f / sum;

    __half* ob = g_xsa + (size_t)(bh * 32) * N_ + n;
#pragma unroll
    for (int d = 0; d < 32; d++) {
        float o = 0.f;
#pragma unroll
        for (int pq = 0; pq < 16; pq++) {
            float4 v4 = *(const float4*)&Vs[d][pq * 4];
            o += s[pq * 4 + 0] * v4.x + s[pq * 4 + 1] * v4.y +
                 s[pq * 4 + 2] * v4.z + s[pq * 4 + 3] * v4.w;
        }
        ob[(size_t)d * N_] = __float2half(o * isum);
    }
}

// ---------------------------------------------------------------------------
// K5: channel gram, split over n (4 CTAs per bh) with fp32 atomics.
// ---------------------------------------------------------------------------
__global__ __launch_bounds__(256) void k5_gram() {
    int bh = blockIdx.x;
    int sp = blockIdx.y;                          // 0..3, n range sp*1024..+1024
    __shared__ float qcs[32][133], kcs[32][133];
    int tid = threadIdx.x;
    int ddp = tid >> 4, ep = tid & 15;
    float a00 = 0.f, a01 = 0.f, a10 = 0.f, a11 = 0.f;
    const __half* qsrc = g_proj + ((size_t)3 * 2048 + bh * 32) * N_;
    const __half* ksrc = g_proj + ((size_t)4 * 2048 + bh * 32) * N_;

    for (int cc = 0; cc < 8; cc++) {
        int c0 = sp * 1024 + cc * 128;
#pragma unroll
        for (int i = 0; i < 16; i++) {
            int f = tid + i * 256;
            int r = f >> 7, j = f & 127;
            qcs[r][j] = __half2float(qsrc[(size_t)r * N_ + c0 + j]);
            kcs[r][j] = __half2float(ksrc[(size_t)r * N_ + c0 + j]);
        }
        __syncthreads();
#pragma unroll 4
        for (int nn = 0; nn < 128; nn++) {
            float q0 = qcs[2 * ddp][nn], q1 = qcs[2 * ddp + 1][nn];
            float k0 = kcs[2 * ep][nn],  k1 = kcs[2 * ep + 1][nn];
            a00 += q0 * k0; a01 += q0 * k1;
            a10 += q1 * k0; a11 += q1 * k1;
        }
        __syncthreads();
    }
    float* gb = &g_gram[bh * 1024];
    atomicAdd(&gb[(2 * ddp) * 32 + 2 * ep], a00);
    atomicAdd(&gb[(2 * ddp) * 32 + 2 * ep + 1], a01);
    atomicAdd(&gb[(2 * ddp + 1) * 32 + 2 * ep], a10);
    atomicAdd(&gb[(2 * ddp + 1) * 32 + 2 * ep + 1], a11);
}

// K5s: scale + softmax of the gram matrix -> g_attn
__global__ __launch_bounds__(256) void k5s_softmax(const float* __restrict__ temp_sc) {
    int bh = blockIdx.x;
    int h = bh & 7;
    __shared__ float att[32][33];
    __shared__ float ivqs[32], ivks[32];
    int tid = threadIdx.x;
    if (tid < 32) ivqs[tid] = inv_norm(g_sumsq[2048 + bh * 32 + tid]);
    else if (tid < 64) ivks[tid - 32] = inv_norm(g_sumsq[4096 + bh * 32 + tid - 32]);
    __syncthreads();
    float temp = temp_sc[h];
#pragma unroll
    for (int i = 0; i < 4; i++) {
        int idx = tid + i * 256;
        int r = idx >> 5, c = idx & 31;
        att[r][c] = g_gram[bh * 1024 + idx] * ivqs[r] * ivks[c] * temp;
    }
    __syncthreads();
    int w = tid >> 5, l = tid & 31;
#pragma unroll
    for (int r0 = 0; r0 < 4; r0++) {
        int r = w * 4 + r0;
        float v = att[r][l];
        float m = v;
#pragma unroll
        for (int o = 16; o > 0; o >>= 1) m = fmaxf(m, __shfl_xor_sync(0xffffffffu, m, o));
        float e = fexp(v - m);
        float sum = e;
#pragma unroll
        for (int o = 16; o > 0; o >>= 1) sum += __shfl_xor_sync(0xffffffffu, sum, o);
        g_attn[bh * 1024 + r * 32 + l] = e / sum;
    }
}

// ---------------------------------------------------------------------------
// K6: combine
// ---------------------------------------------------------------------------
__global__ __launch_bounds__(128) void k6_combine(float* __restrict__ out) {
    int ch = blockIdx.x;
    int bh = blockIdx.y;
    int b = bh >> 3, h = bh & 7;
    __shared__ float vcs[32][128];
    __shared__ float sas[128][33];
    __shared__ float att[1024];
    int tid = threadIdx.x;

    const __half* vsrc = g_proj + ((size_t)5 * 2048 + bh * 32) * N_ + ch * 128;
#pragma unroll
    for (int i = 0; i < 32; i++) {
        int f = tid + i * 128;
        int e = f >> 7, j = f & 127;
        vcs[e][j] = __half2float(vsrc[(size_t)e * N_ + j]);
    }
#pragma unroll
    for (int i = 0; i < 32; i++) {
        int f = tid + i * 128;
        int tp = f >> 5, dc = f & 31;
        sas[tp][dc] = __half2float(g_xsa[((size_t)(b * 8 + (tp >> 4)) * 32 + ch) * N_ +
                                         (tp & 15) * 256 + h * 32 + dc]);
    }
#pragma unroll
    for (int i = 0; i < 8; i++) att[tid + i * 128] = g_attn[bh * 1024 + tid + i * 128];
    __syncthreads();

    float acc[32];
#pragma unroll
    for (int dc = 0; dc < 32; dc++) acc[dc] = 0.f;
#pragma unroll 4
    for (int e = 0; e < 32; e++) {
        float v = vcs[e][tid];
#pragma unroll
        for (int dc = 0; dc < 32; dc++) acc[dc] += att[dc * 32 + e] * v;
    }
    float* ob = out + (size_t)(b * 256 + h * 32) * N_ + ch * 128 + tid;
#pragma unroll
    for (int dc = 0; dc < 32; dc++) ob[(size_t)dc * N_] = acc[dc] + sas[tid][dc];
}

// ---------------------------------------------------------------------------
extern "C" void kernel_launch(void* const* d_in, const int* in_sizes, int n_in,
                              void* d_out, int out_size) {
    const float* x    = (const float*)d_in[0];
    const float* Wsa  = (const float*)d_in[1];
    const float* EF   = (const float*)d_in[2];
    const float* t2sa = (const float*)d_in[3];
    const float* Wsc  = (const float*)d_in[4];
    const float* tsc  = (const float*)d_in[5];
    float* out = (float*)d_out;

    const int k1_smem = 3 * 2 * K1_TILE_HALVES * (int)sizeof(__half);  // 61440
    cudaFuncSetAttribute(k1_mma, cudaFuncAttributeMaxDynamicSharedMemorySize, k1_smem);

    k0w_pack<<<1536, 256>>>(Wsa, Wsc);
    k0x_pack<<<dim3(32, 8), 128>>>(x);
    k0e_pack<<<64, 256>>>(EF);
    k1_mma<<<dim3(32, 12, 8), 256, k1_smem>>>();
    k3_mma<<<dim3(32, 8), 256>>>();
    k3r_reduce<<<1024, 256>>>();
    k4_spatial<<<dim3(16, 64), 256>>>(t2sa);
    k5_gram<<<dim3(64, 4), 256>>>();
    k5s_softmax<<<64, 256>>>(tsc);
    k6_combine<<<dim3(32, 64), 128>>>(out);
}

// round 12
// speedup vs baseline: 3.6397x; 1.2199x over previous
#include <cuda_runtime.h>
#include <cuda_bf16.h>
#include <cuda_fp16.h>
#include <math.h>
#include <stdint.h>

// Problem constants
#define B_ 8
#define C_ 256
#define N_ 4096
#define H_ 8
#define D_ 32
#define P_ 64

// Scratch (device globals; allocation-free contract)
// g_proj layout: [slab][b][row256][n] (fp16), slab: 0=q_sa,1=k_sa,2=v_sa,3=q_c,4=k_c,5=v_c
__device__ __half g_proj[6u * 8u * 256u * 4096u];     // 100 MB
__device__ float g_sumsq[3 * 2048];                   // row sum-of-squares (atomic)
__device__ float g_kvp[8][2 * 64 * 32 * 64];          // K-split partials [sp][row*64+p]
__device__ float g_kv[2 * 64 * 32 * 64];
__device__ float g_gram[64 * 32 * 32];                // channel gram partial sums (atomic)
__device__ float g_attn[64 * 32 * 32];
__device__ __half g_xsa[8u * 8u * 32u * 4096u];       // spatial out [b][h][d][n], fp16

// fp16 operands for the tensor-core GEMMs
__device__ __half g_Wh[1536 * 256];
__device__ __half g_xh[8u * 4096u * 256u];            // [b][n][c]  (transposed)
__device__ __half g_EFh[64 * 4096];                   // EF transposed: [p][n]

// ---------------------------------------------------------------------------
// helpers
// ---------------------------------------------------------------------------
__device__ __forceinline__ uint32_t smem_u32(const void* p) {
    uint32_t a;
    asm("{ .reg .u64 t; cvta.to.shared.u64 t, %1; cvt.u32.u64 %0, t; }" : "=r"(a) : "l"(p));
    return a;
}
#define CP_ASYNC16(dst, src) \
    asm volatile("cp.async.cg.shared.global [%0], [%1], 16;" :: "r"(dst), "l"(src))
#define CP_COMMIT() asm volatile("cp.async.commit_group;" ::: "memory")
#define CP_WAITG1() asm volatile("cp.async.wait_group 1;" ::: "memory")

__device__ __forceinline__ void mma_f16(float* d, const uint32_t* a, const uint32_t* bb) {
    asm volatile(
        "mma.sync.aligned.m16n8k16.row.col.f32.f16.f16.f32 "
        "{%0,%1,%2,%3}, {%4,%5,%6,%7}, {%8,%9}, {%0,%1,%2,%3};"
        : "+f"(d[0]), "+f"(d[1]), "+f"(d[2]), "+f"(d[3])
        : "r"(a[0]), "r"(a[1]), "r"(a[2]), "r"(a[3]), "r"(bb[0]), "r"(bb[1]));
}
__device__ __forceinline__ void ldsm_x4(uint32_t& r0, uint32_t& r1, uint32_t& r2,
                                        uint32_t& r3, uint32_t addr) {
    asm volatile("ldmatrix.sync.aligned.m8n8.x4.shared.b16 {%0,%1,%2,%3}, [%4];"
                 : "=r"(r0), "=r"(r1), "=r"(r2), "=r"(r3) : "r"(addr));
}
__device__ __forceinline__ void ldsm_x4t(uint32_t& r0, uint32_t& r1, uint32_t& r2,
                                         uint32_t& r3, uint32_t addr) {
    asm volatile("ldmatrix.sync.aligned.m8n8.x4.trans.shared.b16 {%0,%1,%2,%3}, [%4];"
                 : "=r"(r0), "=r"(r1), "=r"(r2), "=r"(r3) : "r"(addr));
}
__device__ __forceinline__ void ldsm_x2(uint32_t& r0, uint32_t& r1, uint32_t addr) {
    asm volatile("ldmatrix.sync.aligned.m8n8.x2.shared.b16 {%0,%1}, [%2];"
                 : "=r"(r0), "=r"(r1) : "r"(addr));
}

// FFMA-only exp (avoids MUFU pipe), ~2e-6 relative accuracy.
__device__ __forceinline__ float fexp(float x) {
    const float L2E = 1.4426950408889634f;
    float t = fmaf(x, L2E, 12582912.0f);
    float n = t - 12582912.0f;
    float f = fmaf(x, L2E, -n);
    float p = 1.33978035e-3f;
    p = fmaf(p, f, 9.67770915e-3f);
    p = fmaf(p, f, 5.55041086e-2f);
    p = fmaf(p, f, 2.40226507e-1f);
    p = fmaf(p, f, 6.93147182e-1f);
    p = fmaf(p, f, 1.0f);
    int e = __float2int_rn(n);
    if (e < -126) e = -126;
    if (e > 126) e = 126;
    return __int_as_float((e + 127) << 23) * p;
}

__device__ __forceinline__ float inv_norm(float ss) {
    return 1.f / fmaxf(sqrtf(ss), 1e-12f);
}

// ---------------------------------------------------------------------------
// K0w: pack weights into fp16 (GEMM row order) + zero accumulators.
// ---------------------------------------------------------------------------
__global__ __launch_bounds__(256) void k0w_pack(const float* __restrict__ Wsa,
                                                const float* __restrict__ Wsc) {
    int e = blockIdx.x * 256 + threadIdx.x;       // 0 .. 393215
    if (e < 3 * 2048) g_sumsq[e] = 0.f;
    if (e < 64 * 32 * 32) g_gram[e] = 0.f;
    int r = e >> 8, c = e & 255;
    int p = (r >= 768) ? 1 : 0;
    int rr = r - p * 768;
    int t = rr >> 8;
    const float* Wp = p ? Wsc : Wsa;
    int srow = rr + ((p == 0 && t == 2) ? 256 : 0);
    g_Wh[e] = __float2half(Wp[(size_t)srow * 256 + c]);
}

// ---------------------------------------------------------------------------
// K0x: transpose x [b][c][n] -> [b][n][c], fp16.
// ---------------------------------------------------------------------------
__global__ __launch_bounds__(128) void k0x_pack(const float* __restrict__ x) {
    int n0 = blockIdx.x * 128;
    int b = blockIdx.y;
    __shared__ float sm[64][132];
    int tid = threadIdx.x;
    const float* xb = x + (size_t)b * C_ * N_;

    for (int c0 = 0; c0 < 256; c0 += 64) {
#pragma unroll
        for (int i = 0; i < 16; i++) {
            int u = tid + i * 128;
            int c = u >> 5, nq = u & 31;
            *(float4*)&sm[c][nq * 4] =
                *(const float4*)(xb + (size_t)(c0 + c) * N_ + n0 + nq * 4);
        }
        __syncthreads();
        uint32_t buf[32];
#pragma unroll
        for (int c = 0; c < 64; c += 2) {
            __half2 hv = __floats2half2_rn(sm[c][tid], sm[c + 1][tid]);
            buf[c >> 1] = *(uint32_t*)&hv;
        }
        size_t obase = ((size_t)b * 4096 + n0 + tid) * 256 + c0;
#pragma unroll
        for (int j = 0; j < 8; j++)
            *(uint4*)&g_xh[obase + j * 8] = *(uint4*)&buf[j * 4];
        __syncthreads();
    }
}

// ---------------------------------------------------------------------------
// K0e: transpose EF [n][p] fp32 -> g_EFh [p][n] fp16.
// ---------------------------------------------------------------------------
__global__ __launch_bounds__(256) void k0e_pack(const float* __restrict__ EF) {
    __shared__ float tile[64][65];
    int n0 = blockIdx.x * 64;
    int tid = threadIdx.x;
#pragma unroll
    for (int i = 0; i < 16; i++) {
        int u = tid + i * 256;
        int r = u >> 6, c = u & 63;
        tile[c][r] = EF[(size_t)(n0 + r) * 64 + c];
    }
    __syncthreads();
#pragma unroll
    for (int i = 0; i < 16; i++) {
        int u = tid + i * 256;
        int p = u >> 6, j = u & 63;
        g_EFh[(size_t)p * 4096 + n0 + j] = __float2half(tile[p][j]);
    }
}

// ---------------------------------------------------------------------------
// K1: fp16 mma.sync GEMM with ldmatrix + 3-stage cp.async pipeline.
// Prefetch issued BEFORE the step's compute (buffer freed by the barrier).
// ---------------------------------------------------------------------------
#define K1_TSTRIDE 40
#define K1_TILE_HALVES (128 * K1_TSTRIDE)

__global__ __launch_bounds__(256) void k1_mma() {
    extern __shared__ __half sm1[];
    const int n0 = blockIdx.x * 128;
    const int my = blockIdx.y;                  // 0..11
    const int b  = blockIdx.z;
    const int m0 = my * 128;

    const int tid = threadIdx.x;
    const int wid = tid >> 5, lane = tid & 31;
    const int wm = (wid & 1) * 64, wn = (wid >> 1) * 32;
    const int g = lane >> 2, t4 = lane & 3;

    const int a_row = lane & 15, a_col = (lane >> 4) * 8;
    const int b_row = lane & 7,  b_col = ((lane >> 3) & 1) * 8;

#define TILE(buf, t) (sm1 + ((buf) * 2 + (t)) * K1_TILE_HALVES)

    float acc[4][4][4];
#pragma unroll
    for (int mt = 0; mt < 4; mt++)
#pragma unroll
        for (int nt = 0; nt < 4; nt++)
#pragma unroll
            for (int j = 0; j < 4; j++) acc[mt][nt][j] = 0.f;

    const int lr0 = tid >> 2;
    const int ls0 = (tid & 3) * 8;

#define LOAD_STEP(kc, buf)                                                              \
    do {                                                                                \
        int _k0 = (kc) * 32;                                                            \
        const __half* _A = g_Wh + (size_t)m0 * 256 + _k0;                               \
        const __half* _B = g_xh + ((size_t)b * 4096 + n0) * 256 + _k0;                  \
        CP_ASYNC16(smem_u32(TILE(buf,0) + lr0 * K1_TSTRIDE + ls0), _A + (size_t)lr0 * 256 + ls0); \
        CP_ASYNC16(smem_u32(TILE(buf,0) + (lr0+64) * K1_TSTRIDE + ls0), _A + (size_t)(lr0+64) * 256 + ls0); \
        CP_ASYNC16(smem_u32(TILE(buf,1) + lr0 * K1_TSTRIDE + ls0), _B + (size_t)lr0 * 256 + ls0); \
        CP_ASYNC16(smem_u32(TILE(buf,1) + (lr0+64) * K1_TSTRIDE + ls0), _B + (size_t)(lr0+64) * 256 + ls0); \
    } while (0)

    LOAD_STEP(0, 0); CP_COMMIT();
    LOAD_STEP(1, 1); CP_COMMIT();

    for (int s = 0; s < 8; s++) {
        const int buf = s % 3;
        CP_WAITG1();
        __syncthreads();

        if (s + 2 < 8) LOAD_STEP(s + 2, (s + 2) % 3);
        CP_COMMIT();

#pragma unroll
        for (int h = 0; h < 2; h++) {
            uint32_t af[4][4], bfr[4][2];
            const __half* Abase = TILE(buf, 0) + (size_t)a_row * K1_TSTRIDE + h * 16 + a_col;
            const __half* Bbase = TILE(buf, 1) + (size_t)b_row * K1_TSTRIDE + h * 16 + b_col;
#pragma unroll
            for (int mt = 0; mt < 4; mt++)
                ldsm_x4(af[mt][0], af[mt][1], af[mt][2], af[mt][3],
                        smem_u32(Abase + (wm + mt * 16) * K1_TSTRIDE));
#pragma unroll
            for (int nt = 0; nt < 4; nt++)
                ldsm_x2(bfr[nt][0], bfr[nt][1],
                        smem_u32(Bbase + (wn + nt * 8) * K1_TSTRIDE));
#pragma unroll
            for (int mt = 0; mt < 4; mt++)
#pragma unroll
                for (int nt = 0; nt < 4; nt++)
                    mma_f16(acc[mt][nt], af[mt], bfr[nt]);
        }
    }
#undef LOAD_STEP
#undef TILE

    // epilogue -> g_proj (fp16) + fused sumsq for slabs 0,3,4
    const int slab = my >> 1;
    const int rb = (my & 1) * 128;
    const int which = (slab == 0) ? 0 : (slab == 3 ? 1 : (slab == 4 ? 2 : -1));
#pragma unroll
    for (int mt = 0; mt < 4; mt++) {
        int r0 = rb + wm + mt * 16 + g;
        __half* p0 = g_proj + (((size_t)slab * 8 + b) * 256 + r0) * (size_t)N_ + n0 + wn;
        __half* p1 = p0 + 8 * (size_t)N_;
        float ss0 = 0.f, ss1 = 0.f;
#pragma unroll
        for (int nt = 0; nt < 4; nt++) {
            float a0 = acc[mt][nt][0], a1 = acc[mt][nt][1];
            float a2 = acc[mt][nt][2], a3 = acc[mt][nt][3];
            *(__half2*)(p0 + nt * 8 + 2 * t4) = __floats2half2_rn(a0, a1);
            *(__half2*)(p1 + nt * 8 + 2 * t4) = __floats2half2_rn(a2, a3);
            ss0 += a0 * a0 + a1 * a1;
            ss1 += a2 * a2 + a3 * a3;
        }
        if (which >= 0) {
            ss0 += __shfl_xor_sync(0xffffffffu, ss0, 1);
            ss0 += __shfl_xor_sync(0xffffffffu, ss0, 2);
            ss1 += __shfl_xor_sync(0xffffffffu, ss1, 1);
            ss1 += __shfl_xor_sync(0xffffffffu, ss1, 2);
            if (t4 == 0) {
                int row = b * 256 + r0;
                atomicAdd(&g_sumsq[which * 2048 + row], ss0);
                atomicAdd(&g_sumsq[which * 2048 + row + 8], ss1);
            }
        }
    }
}

// ---------------------------------------------------------------------------
// K3: Linformer projection GEMM (ldmatrix + 3-stage, prefetch-first).
// ---------------------------------------------------------------------------
#define K3_STRIDE 40
__global__ __launch_bounds__(256) void k3_mma() {
    __shared__ __half As[3][128][K3_STRIDE];
    __shared__ __half Bs[3][64][K3_STRIDE];
    const int m0 = blockIdx.x * 128;
    const int sp = blockIdx.y;
    const int kb = sp * 512;

    const int tid = threadIdx.x;
    const int wid = tid >> 5, lane = tid & 31;
    const int wm = (wid >> 1) * 32;
    const int wn = (wid & 1) * 32;
    const int g = lane >> 2, t4 = lane & 3;

    const int a_row = lane & 15, a_col = (lane >> 4) * 8;
    const int b_row = lane & 7,  b_col = ((lane >> 3) & 1) * 8;

    const __half* Ag = g_proj + (size_t)2048 * N_;

    float acc[2][4][4];
#pragma unroll
    for (int mt = 0; mt < 2; mt++)
#pragma unroll
        for (int nt = 0; nt < 4; nt++)
#pragma unroll
            for (int j = 0; j < 4; j++) acc[mt][nt][j] = 0.f;

    const int lr = tid >> 2;
    const int ls = (tid & 3) * 8;

#define K3_LOAD(kc, buf)                                                                \
    do {                                                                                \
        int _k0 = kb + (kc) * 32;                                                       \
        const __half* _A = Ag + (size_t)m0 * 4096 + _k0;                                \
        const __half* _B = g_EFh + _k0;                                                 \
        CP_ASYNC16(smem_u32(&As[buf][lr][ls]), _A + (size_t)lr * 4096 + ls);            \
        CP_ASYNC16(smem_u32(&As[buf][lr + 64][ls]), _A + (size_t)(lr + 64) * 4096 + ls);\
        CP_ASYNC16(smem_u32(&Bs[buf][lr][ls]), _B + (size_t)lr * 4096 + ls);            \
    } while (0)

    K3_LOAD(0, 0); CP_COMMIT();
    K3_LOAD(1, 1); CP_COMMIT();

    for (int s = 0; s < 16; s++) {
        const int buf = s % 3;
        CP_WAITG1();
        __syncthreads();

        if (s + 2 < 16) K3_LOAD(s + 2, (s + 2) % 3);
        CP_COMMIT();

#pragma unroll
        for (int h = 0; h < 2; h++) {
            uint32_t af[2][4], bfr[4][2];
            const __half* Abase = &As[buf][a_row][h * 16 + a_col];
            const __half* Bbase = &Bs[buf][b_row][h * 16 + b_col];
#pragma unroll
            for (int mt = 0; mt < 2; mt++)
                ldsm_x4(af[mt][0], af[mt][1], af[mt][2], af[mt][3],
                        smem_u32(Abase + (wm + mt * 16) * K3_STRIDE));
#pragma unroll
            for (int nt = 0; nt < 4; nt++)
                ldsm_x2(bfr[nt][0], bfr[nt][1],
                        smem_u32(Bbase + (wn + nt * 8) * K3_STRIDE));
#pragma unroll
            for (int mt = 0; mt < 2; mt++)
#pragma unroll
                for (int nt = 0; nt < 4; nt++)
                    mma_f16(acc[mt][nt], af[mt], bfr[nt]);
        }
    }
#undef K3_LOAD

#pragma unroll
    for (int mt = 0; mt < 2; mt++) {
        int row = m0 + wm + mt * 16 + g;
        float* p0 = &g_kvp[sp][(size_t)row * 64 + wn];
        float* p1 = p0 + 8 * 64;
#pragma unroll
        for (int nt = 0; nt < 4; nt++) {
            *(float2*)(p0 + nt * 8 + 2 * t4) = make_float2(acc[mt][nt][0], acc[mt][nt][1]);
            *(float2*)(p1 + nt * 8 + 2 * t4) = make_float2(acc[mt][nt][2], acc[mt][nt][3]);
        }
    }
}

__global__ __launch_bounds__(256) void k3r_reduce() {
    int i = blockIdx.x * 256 + threadIdx.x;
    float s = 0.f;
#pragma unroll
    for (int sp = 0; sp < 8; sp++) s += g_kvp[sp][i];
    g_kv[i] = s;
}

// ---------------------------------------------------------------------------
// K4: spatial attention on tensor cores (flash-style, fused softmax).
// Per CTA: 128 tokens x one bh. 4 warps, each 32 tokens.
// GEMM1: S[n][p] = Q^T[n][d] x Ksc[d][p], Ksc pre-scaled by iv_d*temp.
// In-register softmax over p, C->A repack, GEMM2: O = P x V^T.
// ---------------------------------------------------------------------------
__global__ __launch_bounds__(128) void k4_mma(const float* __restrict__ temp2_sa) {
    __shared__ __align__(16) __half sQ[32][136];   // [d][n]
    __shared__ __align__(16) __half sK[64][40];    // [p][d], pre-scaled
    __shared__ __align__(16) __half sV[32][72];    // [d][p]
    __shared__ __align__(16) __half sO[32][136];   // [d][n]
    __shared__ float ivs[32];
    const int tid = threadIdx.x;
    const int lane = tid & 31, w = tid >> 5;
    const int n0 = blockIdx.x * 128;
    const int bh = blockIdx.y;
    const int h = bh & 7;
    const int g = lane >> 2, t4 = lane & 3;

    if (tid < 32) ivs[tid] = inv_norm(g_sumsq[bh * 32 + tid]);
    __syncthreads();
    const float temp = temp2_sa[h];

    // K scaled (transpose to [p][d]) and V ([d][p])
#pragma unroll
    for (int i = 0; i < 16; i++) {
        int u = tid + i * 128;
        int d = u >> 6, p = u & 63;
        sK[p][d] = __float2half(g_kv[bh * 2048 + d * 64 + p] * ivs[d] * temp);
        sV[d][p] = __float2half(g_kv[(64 + bh) * 2048 + d * 64 + p]);
    }
    // Q tile [32 d][128 n]
    const __half* qb = g_proj + (size_t)(bh * 32) * N_ + n0;
#pragma unroll
    for (int i = 0; i < 4; i++) {
        int u = tid + i * 128;
        int d = u >> 4, sg = u & 15;
        *(uint4*)&sQ[d][sg * 8] = *(const uint4*)(qb + (size_t)d * N_ + sg * 8);
    }
    __syncthreads();

    // ---- GEMM1: S = Q^T x Ksc  (M=32 rows/warp, N=64, K=32) ----
    const int a_d = (lane & 7) | (((lane >> 4) & 1) << 3);     // trans-A d row
    const int a_noff = ((lane >> 3) & 1) * 8;                  // trans-A n col off
    const int b_row = lane & 7, b_koff = ((lane >> 3) & 1) * 8;

    float acc[2][8][4];
#pragma unroll
    for (int mt = 0; mt < 2; mt++)
#pragma unroll
        for (int nt = 0; nt < 8; nt++)
#pragma unroll
            for (int j = 0; j < 4; j++) acc[mt][nt][j] = 0.f;

#pragma unroll
    for (int h2 = 0; h2 < 2; h2++) {
        uint32_t af[2][4], bfr[8][2];
#pragma unroll
        for (int mt = 0; mt < 2; mt++)
            ldsm_x4t(af[mt][0], af[mt][1], af[mt][2], af[mt][3],
                     smem_u32(&sQ[a_d + h2 * 16][w * 32 + mt * 16 + a_noff]));
#pragma unroll
        for (int nt = 0; nt < 8; nt++)
            ldsm_x2(bfr[nt][0], bfr[nt][1],
                    smem_u32(&sK[nt * 8 + b_row][b_koff + h2 * 16]));
#pragma unroll
        for (int mt = 0; mt < 2; mt++)
#pragma unroll
            for (int nt = 0; nt < 8; nt++)
                mma_f16(acc[mt][nt], af[mt], bfr[nt]);
    }

    // ---- softmax over p (64), rows spread over t4 quad ----
    float isr[2][2];
    uint32_t pa[2][4][4];                          // P a-frags [mt][kk][4]
#pragma unroll
    for (int mt = 0; mt < 2; mt++) {
        float m0 = -1e30f, m1 = -1e30f;
#pragma unroll
        for (int nt = 0; nt < 8; nt++) {
            m0 = fmaxf(m0, fmaxf(acc[mt][nt][0], acc[mt][nt][1]));
            m1 = fmaxf(m1, fmaxf(acc[mt][nt][2], acc[mt][nt][3]));
        }
        m0 = fmaxf(m0, __shfl_xor_sync(0xffffffffu, m0, 1));
        m0 = fmaxf(m0, __shfl_xor_sync(0xffffffffu, m0, 2));
        m1 = fmaxf(m1, __shfl_xor_sync(0xffffffffu, m1, 1));
        m1 = fmaxf(m1, __shfl_xor_sync(0xffffffffu, m1, 2));
        float s0 = 0.f, s1 = 0.f;
#pragma unroll
        for (int nt = 0; nt < 8; nt++) {
            acc[mt][nt][0] = fexp(acc[mt][nt][0] - m0);
            acc[mt][nt][1] = fexp(acc[mt][nt][1] - m0);
            acc[mt][nt][2] = fexp(acc[mt][nt][2] - m1);
            acc[mt][nt][3] = fexp(acc[mt][nt][3] - m1);
            s0 += acc[mt][nt][0] + acc[mt][nt][1];
            s1 += acc[mt][nt][2] + acc[mt][nt][3];
        }
        s0 += __shfl_xor_sync(0xffffffffu, s0, 1);
        s0 += __shfl_xor_sync(0xffffffffu, s0, 2);
        s1 += __shfl_xor_sync(0xffffffffu, s1, 1);
        s1 += __shfl_xor_sync(0xffffffffu, s1, 2);
        isr[mt][0] = 1.f / s0;
        isr[mt][1] = 1.f / s1;
        // repack P (unnormalized) into a-frags: kk-th k16 = p tiles 2kk, 2kk+1
#pragma unroll
        for (int kk = 0; kk < 4; kk++) {
            __half2 h0 = __floats2half2_rn(acc[mt][2 * kk][0], acc[mt][2 * kk][1]);
            __half2 h1 = __floats2half2_rn(acc[mt][2 * kk][2], acc[mt][2 * kk][3]);
            __half2 h2a = __floats2half2_rn(acc[mt][2 * kk + 1][0], acc[mt][2 * kk + 1][1]);
            __half2 h3 = __floats2half2_rn(acc[mt][2 * kk + 1][2], acc[mt][2 * kk + 1][3]);
            pa[mt][kk][0] = *(uint32_t*)&h0;
            pa[mt][kk][1] = *(uint32_t*)&h1;
            pa[mt][kk][2] = *(uint32_t*)&h2a;
            pa[mt][kk][3] = *(uint32_t*)&h3;
        }
    }

    // ---- GEMM2: O = P x V^T  (M=32/warp, N=32 d, K=64 p) ----
    float o[2][4][4];
#pragma unroll
    for (int mt = 0; mt < 2; mt++)
#pragma unroll
        for (int nt = 0; nt < 4; nt++)
#pragma unroll
            for (int j = 0; j < 4; j++) o[mt][nt][j] = 0.f;

#pragma unroll
    for (int kk = 0; kk < 4; kk++) {
        uint32_t bfr[4][2];
#pragma unroll
        for (int nt = 0; nt < 4; nt++)
            ldsm_x2(bfr[nt][0], bfr[nt][1],
                    smem_u32(&sV[nt * 8 + b_row][b_koff + kk * 16]));
#pragma unroll
        for (int mt = 0; mt < 2; mt++)
#pragma unroll
            for (int nt = 0; nt < 4; nt++)
                mma_f16(o[mt][nt], pa[mt][kk], bfr[nt]);
    }

    // ---- scale by 1/sum, stage to sO [d][n], write out coalesced ----
#pragma unroll
    for (int mt = 0; mt < 2; mt++) {
        int r0 = w * 32 + mt * 16 + g;
#pragma unroll
        for (int nt = 0; nt < 4; nt++) {
            int d0 = nt * 8 + 2 * t4;
            sO[d0][r0]         = __float2half(o[mt][nt][0] * isr[mt][0]);
            sO[d0 + 1][r0]     = __float2half(o[mt][nt][1] * isr[mt][0]);
            sO[d0][r0 + 8]     = __float2half(o[mt][nt][2] * isr[mt][1]);
            sO[d0 + 1][r0 + 8] = __float2half(o[mt][nt][3] * isr[mt][1]);
        }
    }
    __syncthreads();
    __half* ob = g_xsa + (size_t)(bh * 32) * N_ + n0;
#pragma unroll
    for (int i = 0; i < 4; i++) {
        int u = tid + i * 128;
        int d = u >> 4, sg = u & 15;
        *(uint4*)(ob + (size_t)d * N_ + sg * 8) = *(uint4*)&sO[d][sg * 8];
    }
}

// ---------------------------------------------------------------------------
// K5: channel gram, split over n (4 CTAs per bh) with fp32 atomics.
// ---------------------------------------------------------------------------
__global__ __launch_bounds__(256) void k5_gram() {
    int bh = blockIdx.x;
    int sp = blockIdx.y;
    __shared__ float qcs[32][133], kcs[32][133];
    int tid = threadIdx.x;
    int ddp = tid >> 4, ep = tid & 15;
    float a00 = 0.f, a01 = 0.f, a10 = 0.f, a11 = 0.f;
    const __half* qsrc = g_proj + ((size_t)3 * 2048 + bh * 32) * N_;
    const __half* ksrc = g_proj + ((size_t)4 * 2048 + bh * 32) * N_;

    for (int cc = 0; cc < 8; cc++) {
        int c0 = sp * 1024 + cc * 128;
#pragma unroll
        for (int i = 0; i < 16; i++) {
            int f = tid + i * 256;
            int r = f >> 7, j = f & 127;
            qcs[r][j] = __half2float(qsrc[(size_t)r * N_ + c0 + j]);
            kcs[r][j] = __half2float(ksrc[(size_t)r * N_ + c0 + j]);
        }
        __syncthreads();
#pragma unroll 4
        for (int nn = 0; nn < 128; nn++) {
            float q0 = qcs[2 * ddp][nn], q1 = qcs[2 * ddp + 1][nn];
            float k0 = kcs[2 * ep][nn],  k1 = kcs[2 * ep + 1][nn];
            a00 += q0 * k0; a01 += q0 * k1;
            a10 += q1 * k0; a11 += q1 * k1;
        }
        __syncthreads();
    }
    float* gb = &g_gram[bh * 1024];
    atomicAdd(&gb[(2 * ddp) * 32 + 2 * ep], a00);
    atomicAdd(&gb[(2 * ddp) * 32 + 2 * ep + 1], a01);
    atomicAdd(&gb[(2 * ddp + 1) * 32 + 2 * ep], a10);
    atomicAdd(&gb[(2 * ddp + 1) * 32 + 2 * ep + 1], a11);
}

// K5s: scale + softmax of the gram matrix -> g_attn
__global__ __launch_bounds__(256) void k5s_softmax(const float* __restrict__ temp_sc) {
    int bh = blockIdx.x;
    int h = bh & 7;
    __shared__ float att[32][33];
    __shared__ float ivqs[32], ivks[32];
    int tid = threadIdx.x;
    if (tid < 32) ivqs[tid] = inv_norm(g_sumsq[2048 + bh * 32 + tid]);
    else if (tid < 64) ivks[tid - 32] = inv_norm(g_sumsq[4096 + bh * 32 + tid - 32]);
    __syncthreads();
    float temp = temp_sc[h];
#pragma unroll
    for (int i = 0; i < 4; i++) {
        int idx = tid + i * 256;
        int r = idx >> 5, c = idx & 31;
        att[r][c] = g_gram[bh * 1024 + idx] * ivqs[r] * ivks[c] * temp;
    }
    __syncthreads();
    int w = tid >> 5, l = tid & 31;
#pragma unroll
    for (int r0 = 0; r0 < 4; r0++) {
        int r = w * 4 + r0;
        float v = att[r][l];
        float m = v;
#pragma unroll
        for (int o = 16; o > 0; o >>= 1) m = fmaxf(m, __shfl_xor_sync(0xffffffffu, m, o));
        float e = fexp(v - m);
        float sum = e;
#pragma unroll
        for (int o = 16; o > 0; o >>= 1) sum += __shfl_xor_sync(0xffffffffu, sum, o);
        g_attn[bh * 1024 + r * 32 + l] = e / sum;
    }
}

// ---------------------------------------------------------------------------
// K6: combine
// ---------------------------------------------------------------------------
__global__ __launch_bounds__(128) void k6_combine(float* __restrict__ out) {
    int ch = blockIdx.x;
    int bh = blockIdx.y;
    int b = bh >> 3, h = bh & 7;
    __shared__ float vcs[32][128];
    __shared__ float sas[128][33];
    __shared__ float att[1024];
    int tid = threadIdx.x;

    const __half* vsrc = g_proj + ((size_t)5 * 2048 + bh * 32) * N_ + ch * 128;
#pragma unroll
    for (int i = 0; i < 32; i++) {
        int f = tid + i * 128;
        int e = f >> 7, j = f & 127;
        vcs[e][j] = __half2float(vsrc[(size_t)e * N_ + j]);
    }
#pragma unroll
    for (int i = 0; i < 32; i++) {
        int f = tid + i * 128;
        int tp = f >> 5, dc = f & 31;
        sas[tp][dc] = __half2float(g_xsa[((size_t)(b * 8 + (tp >> 4)) * 32 + ch) * N_ +
                                         (tp & 15) * 256 + h * 32 + dc]);
    }
#pragma unroll
    for (int i = 0; i < 8; i++) att[tid + i * 128] = g_attn[bh * 1024 + tid + i * 128];
    __syncthreads();

    float acc[32];
#pragma unroll
    for (int dc = 0; dc < 32; dc++) acc[dc] = 0.f;
#pragma unroll 4
    for (int e = 0; e < 32; e++) {
        float v = vcs[e][tid];
#pragma unroll
        for (int dc = 0; dc < 32; dc++) acc[dc] += att[dc * 32 + e] * v;
    }
    float* ob = out + (size_t)(b * 256 + h * 32) * N_ + ch * 128 + tid;
#pragma unroll
    for (int dc = 0; dc < 32; dc++) ob[(size_t)dc * N_] = acc[dc] + sas[tid][dc];
}

// ---------------------------------------------------------------------------
extern "C" void kernel_launch(void* const* d_in, const int* in_sizes, int n_in,
                              void* d_out, int out_size) {
    const float* x    = (const float*)d_in[0];
    const float* Wsa  = (const float*)d_in[1];
    const float* EF   = (const float*)d_in[2];
    const float* t2sa = (const float*)d_in[3];
    const float* Wsc  = (const float*)d_in[4];
    const float* tsc  = (const float*)d_in[5];
    float* out = (float*)d_out;

    const int k1_smem = 3 * 2 * K1_TILE_HALVES * (int)sizeof(__half);  // 61440
    cudaFuncSetAttribute(k1_mma, cudaFuncAttributeMaxDynamicSharedMemorySize, k1_smem);

    k0w_pack<<<1536, 256>>>(Wsa, Wsc);
    k0x_pack<<<dim3(32, 8), 128>>>(x);
    k0e_pack<<<64, 256>>>(EF);
    k1_mma<<<dim3(32, 12, 8), 256, k1_smem>>>();
    k3_mma<<<dim3(32, 8), 256>>>();
    k3r_reduce<<<1024, 256>>>();
    k4_mma<<<dim3(32, 64), 128>>>(t2sa);
    k5_gram<<<dim3(64, 4), 256>>>();
    k5s_softmax<<<64, 256>>>(tsc);
    k6_combine<<<dim3(32, 64), 128>>>(out);
}